// round 5
// baseline (speedup 1.0000x reference)
#include <cuda_runtime.h>
#include <cuda_bf16.h>

#define T_TOKENS 8192
#define DM 1024
#define DH 4096
#define NE 8
#define CAP 1280   // int(1.25 * 8192 / 8)

// ---------------- static device scratch (no allocation allowed) ----------------
__device__ __nv_bfloat16 g_bufh[NE * (size_t)CAP * DM]; // dispatched tokens hi
__device__ __nv_bfloat16 g_bufl[NE * (size_t)CAP * DM]; // dispatched tokens lo
__device__ float g_hid [NE * (size_t)CAP * DH];         // hidden activations fp32
__device__ float g_eout[NE * (size_t)CAP * DM];         // expert outputs fp32
__device__ float g_gates[T_TOKENS * NE];
__device__ float g_topval[T_TOKENS];
__device__ int   g_topidx[T_TOKENS];
__device__ int   g_rank [T_TOKENS];
__device__ int   g_used [NE];

// ---------------- PTX helpers (sm_80-level, valid under compute_103) ------
__device__ __forceinline__ unsigned smem_u32(const void* p) {
    unsigned a;
    asm("{ .reg .u64 t; cvta.to.shared.u64 t, %1; cvt.u32.u64 %0, t; }" : "=r"(a) : "l"(p));
    return a;
}
__device__ __forceinline__ void cp16(unsigned dst, const void* src) {
    asm volatile("cp.async.cg.shared.global [%0], [%1], 16;\n" :: "r"(dst), "l"(src));
}
#define CP_COMMIT() asm volatile("cp.async.commit_group;\n" ::: "memory")
#define CP_WAIT(n)  asm volatile("cp.async.wait_group %0;\n" :: "n"(n) : "memory")

__device__ __forceinline__ void ldsm4(unsigned* r, unsigned addr) {
    asm volatile("ldmatrix.sync.aligned.m8n8.x4.shared.b16 {%0,%1,%2,%3}, [%4];\n"
                 : "=r"(r[0]), "=r"(r[1]), "=r"(r[2]), "=r"(r[3]) : "r"(addr));
}
__device__ __forceinline__ void ldsm4t(unsigned* r, unsigned addr) {
    asm volatile("ldmatrix.sync.aligned.m8n8.x4.trans.shared.b16 {%0,%1,%2,%3}, [%4];\n"
                 : "=r"(r[0]), "=r"(r[1]), "=r"(r[2]), "=r"(r[3]) : "r"(addr));
}
__device__ __forceinline__ void mma_bf16(float* d, const unsigned* a, const unsigned* b) {
    asm volatile(
        "mma.sync.aligned.m16n8k16.row.col.f32.bf16.bf16.f32 "
        "{%0,%1,%2,%3}, {%4,%5,%6,%7}, {%8,%9}, {%0,%1,%2,%3};\n"
        : "+f"(d[0]), "+f"(d[1]), "+f"(d[2]), "+f"(d[3])
        : "r"(a[0]), "r"(a[1]), "r"(a[2]), "r"(a[3]), "r"(b[0]), "r"(b[1]));
}
__device__ __forceinline__ unsigned pack2(__nv_bfloat16 a, __nv_bfloat16 b) {
    unsigned short ua = __bfloat16_as_ushort(a), ub = __bfloat16_as_ushort(b);
    return (unsigned)ua | ((unsigned)ub << 16);
}
__device__ __forceinline__ void split4(float4 v, uint2& hi, uint2& lo) {
    __nv_bfloat16 h0 = __float2bfloat16(v.x), h1 = __float2bfloat16(v.y);
    __nv_bfloat16 h2 = __float2bfloat16(v.z), h3 = __float2bfloat16(v.w);
    hi = make_uint2(pack2(h0, h1), pack2(h2, h3));
    lo = make_uint2(pack2(__float2bfloat16(v.x - __bfloat162float(h0)),
                          __float2bfloat16(v.y - __bfloat162float(h1))),
                    pack2(__float2bfloat16(v.z - __bfloat162float(h2)),
                          __float2bfloat16(v.w - __bfloat162float(h3))));
}

// ---------------- router: warp per token ----------------
__global__ __launch_bounds__(256) void router_kernel(
    const float* __restrict__ x,
    const float* __restrict__ rw,
    const float* __restrict__ rb)
{
    int warp = (blockIdx.x * blockDim.x + threadIdx.x) >> 5;
    int lane = threadIdx.x & 31;
    if (warp >= T_TOKENS) return;
    const float* xr = x + (size_t)warp * DM;

    float acc[NE];
    #pragma unroll
    for (int e = 0; e < NE; e++) acc[e] = 0.f;

    #pragma unroll 4
    for (int i = 0; i < DM / 32; i++) {
        int idx = i * 32 + lane;
        float xv = xr[idx];
        const float4* w4 = (const float4*)(rw + idx * NE);
        float4 w0 = w4[0], w1v = w4[1];
        acc[0] += xv * w0.x;  acc[1] += xv * w0.y;
        acc[2] += xv * w0.z;  acc[3] += xv * w0.w;
        acc[4] += xv * w1v.x; acc[5] += xv * w1v.y;
        acc[6] += xv * w1v.z; acc[7] += xv * w1v.w;
    }
    #pragma unroll
    for (int e = 0; e < NE; e++) {
        #pragma unroll
        for (int o = 16; o; o >>= 1)
            acc[e] += __shfl_xor_sync(0xffffffffu, acc[e], o);
    }
    if (lane == 0) {
        float lg[NE];
        float m = -1e30f;
        #pragma unroll
        for (int e = 0; e < NE; e++) { lg[e] = acc[e] + rb[e]; m = fmaxf(m, lg[e]); }
        float g[NE], s = 0.f;
        #pragma unroll
        for (int e = 0; e < NE; e++) { g[e] = __expf(lg[e] - m); s += g[e]; }
        float inv = 1.f / s;
        int   bi = 0;
        float bg = -1.f;
        #pragma unroll
        for (int e = 0; e < NE; e++) {
            g[e] *= inv;
            g_gates[(size_t)warp * NE + e] = g[e];
            if (g[e] > bg) { bg = g[e]; bi = e; }  // strict > => first-max, matches argmax
        }
        g_topidx[warp] = bi;
        g_topval[warp] = bg;
    }
}

// ---------------- scan: single block, ordered per-expert prefix ----------------
__global__ __launch_bounds__(1024) void scan_kernel(float* __restrict__ out, int y_elems)
{
    __shared__ int   sc[NE * 1024];
    __shared__ float sf[1024];
    int tid  = threadIdx.x;
    int base = tid * 8;

    int cnt[NE];
    int eloc[8];
    #pragma unroll
    for (int e = 0; e < NE; e++) cnt[e] = 0;
    #pragma unroll
    for (int j = 0; j < 8; j++) {
        int e = g_topidx[base + j];
        eloc[j] = e;
        cnt[e]++;
    }
    #pragma unroll
    for (int e = 0; e < NE; e++) sc[e * 1024 + tid] = cnt[e];
    __syncthreads();

    for (int off = 1; off < 1024; off <<= 1) {
        int tmp[NE];
        #pragma unroll
        for (int e = 0; e < NE; e++)
            tmp[e] = sc[e * 1024 + tid] + (tid >= off ? sc[e * 1024 + tid - off] : 0);
        __syncthreads();
        #pragma unroll
        for (int e = 0; e < NE; e++) sc[e * 1024 + tid] = tmp[e];
        __syncthreads();
    }

    int off8[NE];
    #pragma unroll
    for (int e = 0; e < NE; e++) off8[e] = sc[e * 1024 + tid] - cnt[e];

    int c2[NE];
    #pragma unroll
    for (int e = 0; e < NE; e++) c2[e] = 0;
    #pragma unroll
    for (int j = 0; j < 8; j++) {
        int e = eloc[j];
        g_rank[base + j] = off8[e] + c2[e];
        c2[e]++;
    }

    float imp[NE];
    #pragma unroll
    for (int e = 0; e < NE; e++) imp[e] = 0.f;
    #pragma unroll
    for (int j = 0; j < 8; j++) {
        const float* gp = &g_gates[(size_t)(base + j) * NE];
        #pragma unroll
        for (int e = 0; e < NE; e++) imp[e] += gp[e];
    }

    float aux = 0.f;
    for (int e = 0; e < NE; e++) {
        sf[tid] = imp[e];
        __syncthreads();
        for (int s = 512; s > 0; s >>= 1) {
            if (tid < s) sf[tid] += sf[tid + s];
            __syncthreads();
        }
        if (tid == 0) {
            int   tot        = sc[e * 1024 + 1023];
            float load       = (float)tot / (float)T_TOKENS;
            float importance = sf[0] / (float)T_TOKENS;
            aux += importance * load;
            int u = tot < CAP ? tot : CAP;
            g_used[e] = u;
            out[y_elems + 1 + e] = (float)u;
        }
        __syncthreads();
    }
    if (tid == 0) out[y_elems] = aux * (float)NE * 0.01f;
}

// ---------------- dispatch: block per token, write bf16 hi/lo ----------------
__global__ __launch_bounds__(256) void dispatch_kernel(const float* __restrict__ x)
{
    int t = blockIdx.x;
    int r = g_rank[t];
    if (r >= CAP) return;
    int e = g_topidx[t];
    float4 v = ((const float4*)(x + (size_t)t * DM))[threadIdx.x];
    uint2 hi, lo;
    split4(v, hi, lo);
    size_t base = ((size_t)e * CAP + r) * (DM / 4) + threadIdx.x;
    ((uint2*)g_bufh)[base] = hi;
    ((uint2*)g_bufl)[base] = lo;
}

// =====================================================================
// ffn1: 128x256 tile, warp 64x64, K=1024 staged 32.
// A (bf16 hi/lo) via cp.async double-buffer; B (fp32 W1) via LDG->split->STS.
// =====================================================================
#define A_PAD 80
#define B1_PAD 528
#define F1_AL 10240
#define F1_BH 20480
#define F1_BL 37376
#define F1_STRIDE 54272
#define F1_SMEM (2 * F1_STRIDE)

__device__ __forceinline__ void f1_loadA(unsigned sbase, const __nv_bfloat16* Ah,
                                         const __nv_bfloat16* Al, int k0, int tid)
{
    #pragma unroll
    for (int l = 0; l < 4; l++) {
        int i   = tid + l * 256;
        int arr = i >> 9;
        int rem = i & 511;
        int row = rem >> 2, c = rem & 3;
        unsigned dst = sbase + (arr ? F1_AL : 0) + row * A_PAD + c * 16;
        const __nv_bfloat16* src = (arr ? Al : Ah) + (size_t)row * DM + k0 + c * 8;
        cp16(dst, src);
    }
    CP_COMMIT();
}

__global__ __launch_bounds__(256, 1) void ffn1(
    const float* __restrict__ W, const float* __restrict__ bias_g)
{
    constexpr int K = DM, NFULL = DH, S = K / 32;
    extern __shared__ __align__(128) char smem[];
    const int e    = blockIdx.z;
    const int row0 = blockIdx.y * 128;
    if (row0 >= g_used[e]) return;
    const int col0 = blockIdx.x * 256;

    const __nv_bfloat16* Ah = g_bufh + ((size_t)e * CAP + row0) * K;
    const __nv_bfloat16* Al = g_bufl + ((size_t)e * CAP + row0) * K;
    const float* Wp = W + (size_t)e * K * NFULL;

    unsigned sb = smem_u32(smem);
    int tid  = threadIdx.x;
    int lane = tid & 31;
    int wid  = tid >> 5;
    int wm = (wid & 1) * 64;
    int wn = (wid >> 1) * 64;

    float acc[4][8][4];
    #pragma unroll
    for (int t = 0; t < 4; t++)
        #pragma unroll
        for (int n = 0; n < 8; n++)
            #pragma unroll
            for (int j = 0; j < 4; j++) acc[t][n][j] = 0.f;

    unsigned a_row  = wm + (lane & 15);
    unsigned a_koff = (lane >> 4) * 16;
    unsigned b_krow = lane & 15;
    unsigned b_ncol = wn + ((lane & 16) ? 8 : 0);

    // B gmem mapping: thread -> (kr = l*4 + tid>>6, c = tid&63) float4 chunks
    int b_kr = tid >> 6;
    int b_c  = tid & 63;

    // prologue: stage 0
    {
        f1_loadA(sb, Ah, Al, 0, tid);
        float4 br[8];
        #pragma unroll
        for (int l = 0; l < 8; l++)
            br[l] = *(const float4*)(Wp + (size_t)(l * 4 + b_kr) * NFULL + col0 + b_c * 4);
        #pragma unroll
        for (int l = 0; l < 8; l++) {
            uint2 hi, lo;
            split4(br[l], hi, lo);
            unsigned off = (l * 4 + b_kr) * B1_PAD + b_c * 8;
            *(uint2*)(smem + F1_BH + off) = hi;
            *(uint2*)(smem + F1_BL + off) = lo;
        }
        CP_WAIT(0);
        __syncthreads();
    }

    #pragma unroll 1
    for (int s = 0; s < S; s++) {
        float4 br[8];
        if (s + 1 < S) {
            int k0n = (s + 1) * 32;
            #pragma unroll
            for (int l = 0; l < 8; l++)
                br[l] = *(const float4*)(Wp + (size_t)(k0n + l * 4 + b_kr) * NFULL + col0 + b_c * 4);
            f1_loadA(sb + ((s + 1) & 1) * F1_STRIDE, Ah, Al, k0n, tid);
        }

        unsigned ab = sb + (s & 1) * F1_STRIDE;
        #pragma unroll
        for (int kk = 0; kk < 2; kk++) {
            unsigned ah[4][4], bh[8][2], bl[8][2];
            #pragma unroll
            for (int t = 0; t < 4; t++)
                ldsm4(ah[t], ab + (a_row + t * 16) * A_PAD + kk * 32 + a_koff);
            #pragma unroll
            for (int h = 0; h < 4; h++) {
                unsigned r[4];
                ldsm4t(r, ab + F1_BH + (kk * 16 + b_krow) * B1_PAD + (b_ncol + h * 16) * 2);
                bh[h * 2][0] = r[0]; bh[h * 2][1] = r[1];
                bh[h * 2 + 1][0] = r[2]; bh[h * 2 + 1][1] = r[3];
            }
            #pragma unroll
            for (int t = 0; t < 4; t++)
                #pragma unroll
                for (int n = 0; n < 8; n++)
                    mma_bf16(acc[t][n], ah[t], bh[n]);
            #pragma unroll
            for (int h = 0; h < 4; h++) {
                unsigned r[4];
                ldsm4t(r, ab + F1_BL + (kk * 16 + b_krow) * B1_PAD + (b_ncol + h * 16) * 2);
                bl[h * 2][0] = r[0]; bl[h * 2][1] = r[1];
                bl[h * 2 + 1][0] = r[2]; bl[h * 2 + 1][1] = r[3];
            }
            #pragma unroll
            for (int t = 0; t < 4; t++)
                #pragma unroll
                for (int n = 0; n < 8; n++)
                    mma_bf16(acc[t][n], ah[t], bl[n]);
            #pragma unroll
            for (int t = 0; t < 4; t++) {
                unsigned al4[4];
                ldsm4(al4, ab + F1_AL + (a_row + t * 16) * A_PAD + kk * 32 + a_koff);
                #pragma unroll
                for (int n = 0; n < 8; n++)
                    mma_bf16(acc[t][n], al4, bh[n]);
            }
        }

        if (s + 1 < S) {
            char* nb = smem + ((s + 1) & 1) * F1_STRIDE;
            #pragma unroll
            for (int l = 0; l < 8; l++) {
                uint2 hi, lo;
                split4(br[l], hi, lo);
                unsigned off = (l * 4 + b_kr) * B1_PAD + b_c * 8;
                *(uint2*)(nb + F1_BH + off) = hi;
                *(uint2*)(nb + F1_BL + off) = lo;
            }
            CP_WAIT(0);
        }
        __syncthreads();
    }

    // epilogue: bias + relu, write fp32 hidden
    const float* bias = bias_g + (size_t)e * NFULL + col0;
    int r0l   = lane >> 2;
    int cpair = (lane & 3) * 2;
    #pragma unroll
    for (int t = 0; t < 4; t++) {
        #pragma unroll
        for (int n = 0; n < 8; n++) {
            int col = wn + n * 8 + cpair;
            float b0 = __ldg(bias + col), b1 = __ldg(bias + col + 1);
            int rowA = row0 + wm + t * 16 + r0l;
            #pragma unroll
            for (int half = 0; half < 2; half++) {
                int rg = rowA + half * 8;
                float v0 = fmaxf(acc[t][n][half * 2]     + b0, 0.f);
                float v1 = fmaxf(acc[t][n][half * 2 + 1] + b1, 0.f);
                size_t idx = ((size_t)e * CAP + rg) * NFULL + col0 + col;
                *(float2*)(g_hid + idx) = make_float2(v0, v1);
            }
        }
    }
}

// =====================================================================
// ffn2: 128x128 tile, warp 64x32, K=4096 staged 32.
// A (fp32 hidden) and B (fp32 W2) both via LDG->split->STS, double-buffered.
// =====================================================================
#define B2_PAD 272
#define F2_AL 10240
#define F2_BH 20480
#define F2_BL 29184
#define F2_STRIDE 37888
#define F2_SMEM (2 * F2_STRIDE)

__global__ __launch_bounds__(256, 1) void ffn2(
    const float* __restrict__ W, const float* __restrict__ bias_g)
{
    constexpr int K = DH, NFULL = DM, S = K / 32;
    extern __shared__ __align__(128) char smem[];
    const int e    = blockIdx.z;
    const int row0 = blockIdx.y * 128;
    if (row0 >= g_used[e]) return;
    const int col0 = blockIdx.x * 128;

    const float* Ap = g_hid + ((size_t)e * CAP + row0) * K;
    const float* Wp = W + (size_t)e * K * NFULL;

    unsigned sb = smem_u32(smem);
    int tid  = threadIdx.x;
    int lane = tid & 31;
    int wid  = tid >> 5;
    int wm = (wid & 1) * 64;
    int wn = (wid >> 1) * 32;

    float acc[4][4][4];
    #pragma unroll
    for (int t = 0; t < 4; t++)
        #pragma unroll
        for (int n = 0; n < 4; n++)
            #pragma unroll
            for (int j = 0; j < 4; j++) acc[t][n][j] = 0.f;

    unsigned a_row  = wm + (lane & 15);
    unsigned a_koff = (lane >> 4) * 16;
    unsigned b_krow = lane & 15;
    unsigned b_ncol = wn + ((lane & 16) ? 8 : 0);

    // A gmem mapping: (row = l*32 + tid>>3, c = tid&7); B: (kr = l*8 + tid>>5, c = tid&31)
    int a_r = tid >> 3, a_c = tid & 7;
    int b_kr = tid >> 5, b_c = tid & 31;

    auto store_stage = [&](char* buf, const float4* ar, const float4* br) {
        #pragma unroll
        for (int l = 0; l < 4; l++) {
            uint2 hi, lo;
            split4(ar[l], hi, lo);
            unsigned off = (l * 32 + a_r) * A_PAD + a_c * 8;
            *(uint2*)(buf + off)         = hi;
            *(uint2*)(buf + F2_AL + off) = lo;
        }
        #pragma unroll
        for (int l = 0; l < 4; l++) {
            uint2 hi, lo;
            split4(br[l], hi, lo);
            unsigned off = (l * 8 + b_kr) * B2_PAD + b_c * 8;
            *(uint2*)(buf + F2_BH + off) = hi;
            *(uint2*)(buf + F2_BL + off) = lo;
        }
    };
    auto load_regs = [&](float4* ar, float4* br, int k0) {
        #pragma unroll
        for (int l = 0; l < 4; l++)
            ar[l] = *(const float4*)(Ap + (size_t)(l * 32 + a_r) * K + k0 + a_c * 4);
        #pragma unroll
        for (int l = 0; l < 4; l++)
            br[l] = *(const float4*)(Wp + (size_t)(k0 + l * 8 + b_kr) * NFULL + col0 + b_c * 4);
    };

    // prologue
    {
        float4 ar[4], br[4];
        load_regs(ar, br, 0);
        store_stage(smem, ar, br);
        __syncthreads();
    }

    #pragma unroll 1
    for (int s = 0; s < S; s++) {
        float4 ar[4], br[4];
        if (s + 1 < S) load_regs(ar, br, (s + 1) * 32);

        unsigned ab = sb + (s & 1) * F2_STRIDE;
        #pragma unroll
        for (int kk = 0; kk < 2; kk++) {
            unsigned ah[4][4], bh[4][2], bl[4][2];
            #pragma unroll
            for (int t = 0; t < 4; t++)
                ldsm4(ah[t], ab + (a_row + t * 16) * A_PAD + kk * 32 + a_koff);
            #pragma unroll
            for (int h = 0; h < 2; h++) {
                unsigned r[4];
                ldsm4t(r, ab + F2_BH + (kk * 16 + b_krow) * B2_PAD + (b_ncol + h * 16) * 2);
                bh[h * 2][0] = r[0]; bh[h * 2][1] = r[1];
                bh[h * 2 + 1][0] = r[2]; bh[h * 2 + 1][1] = r[3];
            }
            #pragma unroll
            for (int t = 0; t < 4; t++)
                #pragma unroll
                for (int n = 0; n < 4; n++)
                    mma_bf16(acc[t][n], ah[t], bh[n]);
            #pragma unroll
            for (int h = 0; h < 2; h++) {
                unsigned r[4];
                ldsm4t(r, ab + F2_BL + (kk * 16 + b_krow) * B2_PAD + (b_ncol + h * 16) * 2);
                bl[h * 2][0] = r[0]; bl[h * 2][1] = r[1];
                bl[h * 2 + 1][0] = r[2]; bl[h * 2 + 1][1] = r[3];
            }
            #pragma unroll
            for (int t = 0; t < 4; t++)
                #pragma unroll
                for (int n = 0; n < 4; n++)
                    mma_bf16(acc[t][n], ah[t], bl[n]);
            #pragma unroll
            for (int t = 0; t < 4; t++) {
                unsigned al4[4];
                ldsm4(al4, ab + F2_AL + (a_row + t * 16) * A_PAD + kk * 32 + a_koff);
                #pragma unroll
                for (int n = 0; n < 4; n++)
                    mma_bf16(acc[t][n], al4, bh[n]);
            }
        }

        if (s + 1 < S)
            store_stage(smem + ((s + 1) & 1) * F2_STRIDE, ar, br);
        __syncthreads();
    }

    // epilogue: bias, write fp32 expert output
    const float* bias = bias_g + (size_t)e * NFULL + col0;
    int r0l   = lane >> 2;
    int cpair = (lane & 3) * 2;
    #pragma unroll
    for (int t = 0; t < 4; t++) {
        #pragma unroll
        for (int n = 0; n < 4; n++) {
            int col = wn + n * 8 + cpair;
            float b0 = __ldg(bias + col), b1 = __ldg(bias + col + 1);
            int rowA = row0 + wm + t * 16 + r0l;
            #pragma unroll
            for (int half = 0; half < 2; half++) {
                int rg = rowA + half * 8;
                float v0 = acc[t][n][half * 2]     + b0;
                float v1 = acc[t][n][half * 2 + 1] + b1;
                size_t idx = ((size_t)e * CAP + rg) * NFULL + col0 + col;
                *(float2*)(g_eout + idx) = make_float2(v0, v1);
            }
        }
    }
}

// ---------------- combine ----------------
__global__ __launch_bounds__(256) void combine_kernel(float* __restrict__ out)
{
    int t = blockIdx.x;
    int r = g_rank[t];
    float4* dst = (float4*)(out + (size_t)t * DM);
    if (r < CAP) {
        int   e = g_topidx[t];
        float v = g_topval[t];
        float4 s = ((const float4*)(g_eout + ((size_t)e * CAP + r) * DM))[threadIdx.x];
        s.x *= v; s.y *= v; s.z *= v; s.w *= v;
        dst[threadIdx.x] = s;
    } else {
        dst[threadIdx.x] = make_float4(0.f, 0.f, 0.f, 0.f);
    }
}

extern "C" void kernel_launch(void* const* d_in, const int* in_sizes, int n_in,
                              void* d_out, int out_size)
{
    const float* x  = (const float*)d_in[0];
    const float* rw = (const float*)d_in[1];
    const float* rb = (const float*)d_in[2];
    const float* w1 = (const float*)d_in[3];
    const float* b1 = (const float*)d_in[4];
    const float* w2 = (const float*)d_in[5];
    const float* b2 = (const float*)d_in[6];
    float* out = (float*)d_out;

    int y_elems = in_sizes[0];

    cudaFuncSetAttribute(ffn1, cudaFuncAttributeMaxDynamicSharedMemorySize, F1_SMEM);
    cudaFuncSetAttribute(ffn2, cudaFuncAttributeMaxDynamicSharedMemorySize, F2_SMEM);

    router_kernel<<<T_TOKENS / 8, 256>>>(x, rw, rb);
    scan_kernel<<<1, 1024>>>(out, y_elems);
    dispatch_kernel<<<T_TOKENS, 256>>>(x);

    ffn1<<<dim3(DH / 256, CAP / 128, NE), 256, F1_SMEM>>>(w1, b1);
    ffn2<<<dim3(DM / 128, CAP / 128, NE), 256, F2_SMEM>>>(w2, b2);

    combine_kernel<<<T_TOKENS, 256>>>(out);
}

// round 6
// speedup vs baseline: 1.1403x; 1.1403x over previous
#include <cuda_runtime.h>
#include <cuda_bf16.h>

#define T_TOKENS 8192
#define DM 1024
#define DH 4096
#define NE 8
#define CAP 1280   // int(1.25 * 8192 / 8)

// ---------------- static device scratch (no allocation allowed) ----------------
__device__ __nv_bfloat16 g_w1h[NE * (size_t)DM * DH];  // W1 hi  [E][K=DM][N=DH]
__device__ __nv_bfloat16 g_w1l[NE * (size_t)DM * DH];  // W1 lo
__device__ __nv_bfloat16 g_w2h[NE * (size_t)DH * DM];  // W2 hi  [E][K=DH][N=DM]
__device__ __nv_bfloat16 g_w2l[NE * (size_t)DH * DM];  // W2 lo
__device__ __nv_bfloat16 g_bufh[NE * (size_t)CAP * DM]; // dispatched tokens hi
__device__ __nv_bfloat16 g_bufl[NE * (size_t)CAP * DM]; // dispatched tokens lo
__device__ __nv_bfloat16 g_hh[NE * (size_t)CAP * DH];   // hidden hi
__device__ __nv_bfloat16 g_hl[NE * (size_t)CAP * DH];   // hidden lo
__device__ float g_eout[NE * (size_t)CAP * DM];         // expert outputs fp32
__device__ float g_gates[T_TOKENS * NE];
__device__ float g_topval[T_TOKENS];
__device__ int   g_topidx[T_TOKENS];
__device__ int   g_rank [T_TOKENS];
__device__ int   g_used [NE];

// ---------------- PTX helpers (sm_80-level, valid under compute_103) ------
__device__ __forceinline__ unsigned smem_u32(const void* p) {
    unsigned a;
    asm("{ .reg .u64 t; cvta.to.shared.u64 t, %1; cvt.u32.u64 %0, t; }" : "=r"(a) : "l"(p));
    return a;
}
__device__ __forceinline__ void cp16(unsigned dst, const void* src) {
    asm volatile("cp.async.cg.shared.global [%0], [%1], 16;\n" :: "r"(dst), "l"(src));
}
#define CP_COMMIT() asm volatile("cp.async.commit_group;\n" ::: "memory")
#define CP_WAIT(n)  asm volatile("cp.async.wait_group %0;\n" :: "n"(n) : "memory")

__device__ __forceinline__ void ldsm4(unsigned* r, unsigned addr) {
    asm volatile("ldmatrix.sync.aligned.m8n8.x4.shared.b16 {%0,%1,%2,%3}, [%4];\n"
                 : "=r"(r[0]), "=r"(r[1]), "=r"(r[2]), "=r"(r[3]) : "r"(addr));
}
__device__ __forceinline__ void ldsm4t(unsigned* r, unsigned addr) {
    asm volatile("ldmatrix.sync.aligned.m8n8.x4.trans.shared.b16 {%0,%1,%2,%3}, [%4];\n"
                 : "=r"(r[0]), "=r"(r[1]), "=r"(r[2]), "=r"(r[3]) : "r"(addr));
}
__device__ __forceinline__ void mma_bf16(float* d, const unsigned* a, const unsigned* b) {
    asm volatile(
        "mma.sync.aligned.m16n8k16.row.col.f32.bf16.bf16.f32 "
        "{%0,%1,%2,%3}, {%4,%5,%6,%7}, {%8,%9}, {%0,%1,%2,%3};\n"
        : "+f"(d[0]), "+f"(d[1]), "+f"(d[2]), "+f"(d[3])
        : "r"(a[0]), "r"(a[1]), "r"(a[2]), "r"(a[3]), "r"(b[0]), "r"(b[1]));
}
__device__ __forceinline__ unsigned pack2(__nv_bfloat16 a, __nv_bfloat16 b) {
    unsigned short ua = __bfloat16_as_ushort(a), ub = __bfloat16_as_ushort(b);
    return (unsigned)ua | ((unsigned)ub << 16);
}

// ---------------- router: warp per token ----------------
__global__ __launch_bounds__(256) void router_kernel(
    const float* __restrict__ x,
    const float* __restrict__ rw,
    const float* __restrict__ rb)
{
    int warp = (blockIdx.x * blockDim.x + threadIdx.x) >> 5;
    int lane = threadIdx.x & 31;
    if (warp >= T_TOKENS) return;
    const float* xr = x + (size_t)warp * DM;

    float acc[NE];
    #pragma unroll
    for (int e = 0; e < NE; e++) acc[e] = 0.f;

    #pragma unroll 4
    for (int i = 0; i < DM / 32; i++) {
        int idx = i * 32 + lane;
        float xv = xr[idx];
        const float4* w4 = (const float4*)(rw + idx * NE);
        float4 w0 = w4[0], w1v = w4[1];
        acc[0] += xv * w0.x;  acc[1] += xv * w0.y;
        acc[2] += xv * w0.z;  acc[3] += xv * w0.w;
        acc[4] += xv * w1v.x; acc[5] += xv * w1v.y;
        acc[6] += xv * w1v.z; acc[7] += xv * w1v.w;
    }
    #pragma unroll
    for (int e = 0; e < NE; e++) {
        #pragma unroll
        for (int o = 16; o; o >>= 1)
            acc[e] += __shfl_xor_sync(0xffffffffu, acc[e], o);
    }
    if (lane == 0) {
        float lg[NE];
        float m = -1e30f;
        #pragma unroll
        for (int e = 0; e < NE; e++) { lg[e] = acc[e] + rb[e]; m = fmaxf(m, lg[e]); }
        float g[NE], s = 0.f;
        #pragma unroll
        for (int e = 0; e < NE; e++) { g[e] = __expf(lg[e] - m); s += g[e]; }
        float inv = 1.f / s;
        int   bi = 0;
        float bg = -1.f;
        #pragma unroll
        for (int e = 0; e < NE; e++) {
            g[e] *= inv;
            g_gates[(size_t)warp * NE + e] = g[e];
            if (g[e] > bg) { bg = g[e]; bi = e; }  // strict > => first-max, matches argmax
        }
        g_topidx[warp] = bi;
        g_topval[warp] = bg;
    }
}

// ---------------- scan: single block, ordered per-expert prefix ----------------
__global__ __launch_bounds__(1024) void scan_kernel(float* __restrict__ out, int y_elems)
{
    __shared__ int   sc[NE * 1024];
    __shared__ float sf[1024];
    int tid  = threadIdx.x;
    int base = tid * 8;

    int cnt[NE];
    int eloc[8];
    #pragma unroll
    for (int e = 0; e < NE; e++) cnt[e] = 0;
    #pragma unroll
    for (int j = 0; j < 8; j++) {
        int e = g_topidx[base + j];
        eloc[j] = e;
        cnt[e]++;
    }
    #pragma unroll
    for (int e = 0; e < NE; e++) sc[e * 1024 + tid] = cnt[e];
    __syncthreads();

    for (int off = 1; off < 1024; off <<= 1) {
        int tmp[NE];
        #pragma unroll
        for (int e = 0; e < NE; e++)
            tmp[e] = sc[e * 1024 + tid] + (tid >= off ? sc[e * 1024 + tid - off] : 0);
        __syncthreads();
        #pragma unroll
        for (int e = 0; e < NE; e++) sc[e * 1024 + tid] = tmp[e];
        __syncthreads();
    }

    int off8[NE];
    #pragma unroll
    for (int e = 0; e < NE; e++) off8[e] = sc[e * 1024 + tid] - cnt[e];

    int c2[NE];
    #pragma unroll
    for (int e = 0; e < NE; e++) c2[e] = 0;
    #pragma unroll
    for (int j = 0; j < 8; j++) {
        int e = eloc[j];
        g_rank[base + j] = off8[e] + c2[e];
        c2[e]++;
    }

    float imp[NE];
    #pragma unroll
    for (int e = 0; e < NE; e++) imp[e] = 0.f;
    #pragma unroll
    for (int j = 0; j < 8; j++) {
        const float* gp = &g_gates[(size_t)(base + j) * NE];
        #pragma unroll
        for (int e = 0; e < NE; e++) imp[e] += gp[e];
    }

    float aux = 0.f;
    for (int e = 0; e < NE; e++) {
        sf[tid] = imp[e];
        __syncthreads();
        for (int s = 512; s > 0; s >>= 1) {
            if (tid < s) sf[tid] += sf[tid + s];
            __syncthreads();
        }
        if (tid == 0) {
            int   tot        = sc[e * 1024 + 1023];
            float load       = (float)tot / (float)T_TOKENS;
            float importance = sf[0] / (float)T_TOKENS;
            aux += importance * load;
            int u = tot < CAP ? tot : CAP;
            g_used[e] = u;
            out[y_elems + 1 + e] = (float)u;
        }
        __syncthreads();
    }
    if (tid == 0) out[y_elems] = aux * (float)NE * 0.01f;
}

// ---------------- dispatch: block per token, write bf16 hi/lo ----------------
__global__ __launch_bounds__(256) void dispatch_kernel(const float* __restrict__ x)
{
    int t = blockIdx.x;
    int r = g_rank[t];
    if (r >= CAP) return;
    int e = g_topidx[t];
    float4 v = ((const float4*)(x + (size_t)t * DM))[threadIdx.x];
    __nv_bfloat16 h0 = __float2bfloat16(v.x), h1 = __float2bfloat16(v.y);
    __nv_bfloat16 h2 = __float2bfloat16(v.z), h3 = __float2bfloat16(v.w);
    __nv_bfloat16 l0 = __float2bfloat16(v.x - __bfloat162float(h0));
    __nv_bfloat16 l1 = __float2bfloat16(v.y - __bfloat162float(h1));
    __nv_bfloat16 l2 = __float2bfloat16(v.z - __bfloat162float(h2));
    __nv_bfloat16 l3 = __float2bfloat16(v.w - __bfloat162float(h3));
    size_t base = ((size_t)e * CAP + r) * (DM / 4) + threadIdx.x;
    ((uint2*)g_bufh)[base] = make_uint2(pack2(h0, h1), pack2(h2, h3));
    ((uint2*)g_bufl)[base] = make_uint2(pack2(l0, l1), pack2(l2, l3));
}

// ---------------- weight hi/lo split (layout preserved [E][K][N]) ----------------
template<bool ISW1>
__global__ __launch_bounds__(256) void convert_split(const float* __restrict__ W)
{
    size_t n4 = (size_t)NE * DM * DH / 4;
    __nv_bfloat16* Th = ISW1 ? g_w1h : g_w2h;
    __nv_bfloat16* Tl = ISW1 ? g_w1l : g_w2l;
    for (size_t i = (size_t)blockIdx.x * blockDim.x + threadIdx.x; i < n4;
         i += (size_t)gridDim.x * blockDim.x) {
        float4 v = ((const float4*)W)[i];
        __nv_bfloat16 h0 = __float2bfloat16(v.x), h1 = __float2bfloat16(v.y);
        __nv_bfloat16 h2 = __float2bfloat16(v.z), h3 = __float2bfloat16(v.w);
        __nv_bfloat16 l0 = __float2bfloat16(v.x - __bfloat162float(h0));
        __nv_bfloat16 l1 = __float2bfloat16(v.y - __bfloat162float(h1));
        __nv_bfloat16 l2 = __float2bfloat16(v.z - __bfloat162float(h2));
        __nv_bfloat16 l3 = __float2bfloat16(v.w - __bfloat162float(h3));
        ((uint2*)Th)[i] = make_uint2(pack2(h0, h1), pack2(h2, h3));
        ((uint2*)Tl)[i] = make_uint2(pack2(l0, l1), pack2(l2, l3));
    }
}

// ---------------- mma.sync grouped GEMM ----------------
// Block tile 128(m) x 256(n), 512 threads, warp tile 64x32 (16 warps, 2x8),
// k-staged 32, 3-stage cp.async pipeline.
#define A_PAD 80
#define B_PAD 528
#define OFF_AH 0
#define OFF_AL 10240
#define OFF_BH 20480
#define OFF_BL 37376
#define STAGE_STRIDE 54272
#define FFN_SMEM (3 * STAGE_STRIDE)

template<int K, int NFULL>
__device__ __forceinline__ void load_stage(
    unsigned sbase, const __nv_bfloat16* Ah, const __nv_bfloat16* Al,
    const __nv_bfloat16* Bh, const __nv_bfloat16* Bl, int k0, int col0, int tid)
{
    #pragma unroll
    for (int l = 0; l < 2; l++) {   // A: 1024 chunks (hi 512 + lo 512)
        int i   = tid + l * 512;
        int arr = i >> 9;
        int rem = i & 511;
        int row = rem >> 2, c = rem & 3;
        unsigned dst = sbase + (arr ? OFF_AL : OFF_AH) + row * A_PAD + c * 16;
        const __nv_bfloat16* src = (arr ? Al : Ah) + (size_t)row * K + k0 + c * 8;
        cp16(dst, src);
    }
    #pragma unroll
    for (int l = 0; l < 4; l++) {   // B: 2048 chunks (hi 1024 + lo 1024)
        int i   = tid + l * 512;
        int arr = i >> 10;
        int rem = i & 1023;
        int kr = rem >> 5, c = rem & 31;
        unsigned dst = sbase + (arr ? OFF_BL : OFF_BH) + kr * B_PAD + c * 16;
        const __nv_bfloat16* src = (arr ? Bl : Bh) + (size_t)(k0 + kr) * NFULL + col0 + c * 8;
        cp16(dst, src);
    }
    CP_COMMIT();
}

template<int K, int NFULL, bool RELU, bool FIRST>
__global__ __launch_bounds__(512, 1) void ffn_mma(const float* __restrict__ bias_g)
{
    constexpr int S = K / 32;

    extern __shared__ __align__(128) char smem[];
    const int e    = blockIdx.z;
    const int row0 = blockIdx.y * 128;
    if (row0 >= g_used[e]) return;
    const int col0 = blockIdx.x * 256;

    const __nv_bfloat16* Ah = (FIRST ? g_bufh : g_hh) + ((size_t)e * CAP + row0) * K;
    const __nv_bfloat16* Al = (FIRST ? g_bufl : g_hl) + ((size_t)e * CAP + row0) * K;
    const __nv_bfloat16* Bh = (FIRST ? g_w1h : g_w2h) + (size_t)e * K * NFULL;
    const __nv_bfloat16* Bl = (FIRST ? g_w1l : g_w2l) + (size_t)e * K * NFULL;

    unsigned sb  = smem_u32(smem);
    int tid  = threadIdx.x;
    int lane = tid & 31;
    int wid  = tid >> 5;
    int wm = (wid & 1) * 64;    // warp m offset (2 warps along m)
    int wn = (wid >> 1) * 32;   // warp n offset (8 warps along n)

    float acc[4][4][4];
    #pragma unroll
    for (int t = 0; t < 4; t++)
        #pragma unroll
        for (int n = 0; n < 4; n++)
            #pragma unroll
            for (int j = 0; j < 4; j++) acc[t][n][j] = 0.f;

    // ldmatrix lane address components
    unsigned a_row  = wm + (lane & 15);
    unsigned a_koff = (lane >> 4) * 16;     // byte offset (k half)
    unsigned b_krow = lane & 15;
    unsigned b_ncol = wn + ((lane & 16) ? 8 : 0);

    load_stage<K, NFULL>(sb, Ah, Al, Bh, Bl, 0, col0, tid);
    load_stage<K, NFULL>(sb + STAGE_STRIDE, Ah, Al, Bh, Bl, 32, col0, tid);

    #pragma unroll 1
    for (int s = 0; s < S; s++) {
        if (s == S - 1) { CP_WAIT(0); } else { CP_WAIT(1); }
        __syncthreads();
        if (s + 2 < S)
            load_stage<K, NFULL>(sb + ((s + 2) % 3) * STAGE_STRIDE, Ah, Al, Bh, Bl,
                                 (s + 2) * 32, col0, tid);
        unsigned ab = sb + (s % 3) * STAGE_STRIDE;
        #pragma unroll
        for (int kk = 0; kk < 2; kk++) {
            unsigned ah[4][4], bh[4][2], bl[4][2];
            #pragma unroll
            for (int t = 0; t < 4; t++)
                ldsm4(ah[t], ab + OFF_AH + (a_row + t * 16) * A_PAD + kk * 32 + a_koff);
            #pragma unroll
            for (int h = 0; h < 2; h++) {
                unsigned r[4];
                ldsm4t(r, ab + OFF_BH + (kk * 16 + b_krow) * B_PAD + (b_ncol + h * 16) * 2);
                bh[h * 2][0] = r[0]; bh[h * 2][1] = r[1];
                bh[h * 2 + 1][0] = r[2]; bh[h * 2 + 1][1] = r[3];
            }
            #pragma unroll
            for (int t = 0; t < 4; t++)
                #pragma unroll
                for (int n = 0; n < 4; n++)
                    mma_bf16(acc[t][n], ah[t], bh[n]);
            #pragma unroll
            for (int h = 0; h < 2; h++) {
                unsigned r[4];
                ldsm4t(r, ab + OFF_BL + (kk * 16 + b_krow) * B_PAD + (b_ncol + h * 16) * 2);
                bl[h * 2][0] = r[0]; bl[h * 2][1] = r[1];
                bl[h * 2 + 1][0] = r[2]; bl[h * 2 + 1][1] = r[3];
            }
            #pragma unroll
            for (int t = 0; t < 4; t++)
                #pragma unroll
                for (int n = 0; n < 4; n++)
                    mma_bf16(acc[t][n], ah[t], bl[n]);
            #pragma unroll
            for (int t = 0; t < 4; t++) {
                unsigned al4[4];
                ldsm4(al4, ab + OFF_AL + (a_row + t * 16) * A_PAD + kk * 32 + a_koff);
                #pragma unroll
                for (int n = 0; n < 4; n++)
                    mma_bf16(acc[t][n], al4, bh[n]);
            }
        }
    }

    // epilogue
    const float* bias = bias_g + (size_t)e * NFULL + col0;
    int r0l   = lane >> 2;
    int cpair = (lane & 3) * 2;
    #pragma unroll
    for (int t = 0; t < 4; t++) {
        #pragma unroll
        for (int n = 0; n < 4; n++) {
            int col = wn + n * 8 + cpair;
            float b0 = __ldg(bias + col), b1 = __ldg(bias + col + 1);
            int rowA = row0 + wm + t * 16 + r0l;
            #pragma unroll
            for (int half = 0; half < 2; half++) {
                int rg = rowA + half * 8;
                float v0 = acc[t][n][half * 2]     + b0;
                float v1 = acc[t][n][half * 2 + 1] + b1;
                if (RELU) { v0 = fmaxf(v0, 0.f); v1 = fmaxf(v1, 0.f); }
                size_t idx = ((size_t)e * CAP + rg) * NFULL + col0 + col;
                if (FIRST) {
                    __nv_bfloat16 h0 = __float2bfloat16(v0), h1 = __float2bfloat16(v1);
                    __nv_bfloat16 l0 = __float2bfloat16(v0 - __bfloat162float(h0));
                    __nv_bfloat16 l1 = __float2bfloat16(v1 - __bfloat162float(h1));
                    ((unsigned*)g_hh)[idx >> 1] = pack2(h0, h1);
                    ((unsigned*)g_hl)[idx >> 1] = pack2(l0, l1);
                } else {
                    *(float2*)(g_eout + idx) = make_float2(v0, v1);
                }
            }
        }
    }
}

// ---------------- combine ----------------
__global__ __launch_bounds__(256) void combine_kernel(float* __restrict__ out)
{
    int t = blockIdx.x;
    int r = g_rank[t];
    float4* dst = (float4*)(out + (size_t)t * DM);
    if (r < CAP) {
        int   e = g_topidx[t];
        float v = g_topval[t];
        float4 s = ((const float4*)(g_eout + ((size_t)e * CAP + r) * DM))[threadIdx.x];
        s.x *= v; s.y *= v; s.z *= v; s.w *= v;
        dst[threadIdx.x] = s;
    } else {
        dst[threadIdx.x] = make_float4(0.f, 0.f, 0.f, 0.f);
    }
}

extern "C" void kernel_launch(void* const* d_in, const int* in_sizes, int n_in,
                              void* d_out, int out_size)
{
    const float* x  = (const float*)d_in[0];
    const float* rw = (const float*)d_in[1];
    const float* rb = (const float*)d_in[2];
    const float* w1 = (const float*)d_in[3];
    const float* b1 = (const float*)d_in[4];
    const float* w2 = (const float*)d_in[5];
    const float* b2 = (const float*)d_in[6];
    float* out = (float*)d_out;

    int y_elems = in_sizes[0];

    cudaFuncSetAttribute(ffn_mma<DM, DH, true,  true >,
                         cudaFuncAttributeMaxDynamicSharedMemorySize, FFN_SMEM);
    cudaFuncSetAttribute(ffn_mma<DH, DM, false, false>,
                         cudaFuncAttributeMaxDynamicSharedMemorySize, FFN_SMEM);

    router_kernel<<<T_TOKENS / 8, 256>>>(x, rw, rb);
    scan_kernel<<<1, 1024>>>(out, y_elems);
    dispatch_kernel<<<T_TOKENS, 256>>>(x);
    convert_split<true ><<<4096, 256>>>(w1);
    convert_split<false><<<4096, 256>>>(w2);

    ffn_mma<DM, DH, true,  true ><<<dim3(DH / 256, CAP / 128, NE), 512, FFN_SMEM>>>(b1);
    ffn_mma<DH, DM, false, false><<<dim3(DM / 256, CAP / 128, NE), 512, FFN_SMEM>>>(b2);

    combine_kernel<<<T_TOKENS, 256>>>(out);
}

// round 8
// speedup vs baseline: 1.5071x; 1.3217x over previous
#include <cuda_runtime.h>
#include <cuda_fp16.h>

#define T_TOKENS 8192
#define DM 1024
#define DH 4096
#define NE 8
#define CAP 1280   // int(1.25 * 8192 / 8)

// ---------------- static device scratch (no allocation allowed) ----------------
__device__ __half g_w1h[NE * (size_t)DM * DH];  // W1 hi  [E][K=DM][N=DH]
__device__ __half g_w1l[NE * (size_t)DM * DH];  // W1 lo
__device__ __half g_w2h[NE * (size_t)DH * DM];  // W2 hi  [E][K=DH][N=DM]
__device__ __half g_w2l[NE * (size_t)DH * DM];  // W2 lo
__device__ __half g_buf[NE * (size_t)CAP * DM]; // dispatched tokens fp16
__device__ __half g_h  [NE * (size_t)CAP * DH]; // hidden activations fp16
__device__ float g_eout[NE * (size_t)CAP * DM]; // expert outputs fp32
__device__ float g_gates[T_TOKENS * NE];
__device__ float g_topval[T_TOKENS];
__device__ int   g_topidx[T_TOKENS];
__device__ int   g_rank [T_TOKENS];
__device__ int   g_used [NE];

// ---------------- PTX helpers (sm_80-level, valid under compute_103) ------
__device__ __forceinline__ unsigned smem_u32(const void* p) {
    unsigned a;
    asm("{ .reg .u64 t; cvta.to.shared.u64 t, %1; cvt.u32.u64 %0, t; }" : "=r"(a) : "l"(p));
    return a;
}
__device__ __forceinline__ void cp16(unsigned dst, const void* src) {
    asm volatile("cp.async.cg.shared.global [%0], [%1], 16;\n" :: "r"(dst), "l"(src));
}
#define CP_COMMIT() asm volatile("cp.async.commit_group;\n" ::: "memory")
#define CP_WAIT(n)  asm volatile("cp.async.wait_group %0;\n" :: "n"(n) : "memory")

__device__ __forceinline__ void ldsm4(unsigned* r, unsigned addr) {
    asm volatile("ldmatrix.sync.aligned.m8n8.x4.shared.b16 {%0,%1,%2,%3}, [%4];\n"
                 : "=r"(r[0]), "=r"(r[1]), "=r"(r[2]), "=r"(r[3]) : "r"(addr));
}
__device__ __forceinline__ void ldsm4t(unsigned* r, unsigned addr) {
    asm volatile("ldmatrix.sync.aligned.m8n8.x4.trans.shared.b16 {%0,%1,%2,%3}, [%4];\n"
                 : "=r"(r[0]), "=r"(r[1]), "=r"(r[2]), "=r"(r[3]) : "r"(addr));
}
__device__ __forceinline__ void mma_f16(float* d, const unsigned* a, const unsigned* b) {
    asm volatile(
        "mma.sync.aligned.m16n8k16.row.col.f32.f16.f16.f32 "
        "{%0,%1,%2,%3}, {%4,%5,%6,%7}, {%8,%9}, {%0,%1,%2,%3};\n"
        : "+f"(d[0]), "+f"(d[1]), "+f"(d[2]), "+f"(d[3])
        : "r"(a[0]), "r"(a[1]), "r"(a[2]), "r"(a[3]), "r"(b[0]), "r"(b[1]));
}
__device__ __forceinline__ unsigned packh2(__half a, __half b) {
    unsigned short ua = __half_as_ushort(a), ub = __half_as_ushort(b);
    return (unsigned)ua | ((unsigned)ub << 16);
}

// ---------------- router: warp per token ----------------
__global__ __launch_bounds__(256) void router_kernel(
    const float* __restrict__ x,
    const float* __restrict__ rw,
    const float* __restrict__ rb)
{
    int warp = (blockIdx.x * blockDim.x + threadIdx.x) >> 5;
    int lane = threadIdx.x & 31;
    if (warp >= T_TOKENS) return;
    const float* xr = x + (size_t)warp * DM;

    float acc[NE];
    #pragma unroll
    for (int e = 0; e < NE; e++) acc[e] = 0.f;

    #pragma unroll 4
    for (int i = 0; i < DM / 32; i++) {
        int idx = i * 32 + lane;
        float xv = xr[idx];
        const float4* w4 = (const float4*)(rw + idx * NE);
        float4 w0 = w4[0], w1v = w4[1];
        acc[0] += xv * w0.x;  acc[1] += xv * w0.y;
        acc[2] += xv * w0.z;  acc[3] += xv * w0.w;
        acc[4] += xv * w1v.x; acc[5] += xv * w1v.y;
        acc[6] += xv * w1v.z; acc[7] += xv * w1v.w;
    }
    #pragma unroll
    for (int e = 0; e < NE; e++) {
        #pragma unroll
        for (int o = 16; o; o >>= 1)
            acc[e] += __shfl_xor_sync(0xffffffffu, acc[e], o);
    }
    if (lane == 0) {
        float lg[NE];
        float m = -1e30f;
        #pragma unroll
        for (int e = 0; e < NE; e++) { lg[e] = acc[e] + rb[e]; m = fmaxf(m, lg[e]); }
        float g[NE], s = 0.f;
        #pragma unroll
        for (int e = 0; e < NE; e++) { g[e] = __expf(lg[e] - m); s += g[e]; }
        float inv = 1.f / s;
        int   bi = 0;
        float bg = -1.f;
        #pragma unroll
        for (int e = 0; e < NE; e++) {
            g[e] *= inv;
            g_gates[(size_t)warp * NE + e] = g[e];
            if (g[e] > bg) { bg = g[e]; bi = e; }  // strict > => first-max, matches argmax
        }
        g_topidx[warp] = bi;
        g_topval[warp] = bg;
    }
}

// ---------------- scan: single block, ordered per-expert prefix ----------------
__global__ __launch_bounds__(1024) void scan_kernel(float* __restrict__ out, int y_elems)
{
    __shared__ int   sc[NE * 1024];
    __shared__ float sf[1024];
    int tid  = threadIdx.x;
    int base = tid * 8;

    int cnt[NE];
    int eloc[8];
    #pragma unroll
    for (int e = 0; e < NE; e++) cnt[e] = 0;
    #pragma unroll
    for (int j = 0; j < 8; j++) {
        int e = g_topidx[base + j];
        eloc[j] = e;
        cnt[e]++;
    }
    #pragma unroll
    for (int e = 0; e < NE; e++) sc[e * 1024 + tid] = cnt[e];
    __syncthreads();

    for (int off = 1; off < 1024; off <<= 1) {
        int tmp[NE];
        #pragma unroll
        for (int e = 0; e < NE; e++)
            tmp[e] = sc[e * 1024 + tid] + (tid >= off ? sc[e * 1024 + tid - off] : 0);
        __syncthreads();
        #pragma unroll
        for (int e = 0; e < NE; e++) sc[e * 1024 + tid] = tmp[e];
        __syncthreads();
    }

    int off8[NE];
    #pragma unroll
    for (int e = 0; e < NE; e++) off8[e] = sc[e * 1024 + tid] - cnt[e];

    int c2[NE];
    #pragma unroll
    for (int e = 0; e < NE; e++) c2[e] = 0;
    #pragma unroll
    for (int j = 0; j < 8; j++) {
        int e = eloc[j];
        g_rank[base + j] = off8[e] + c2[e];
        c2[e]++;
    }

    float imp[NE];
    #pragma unroll
    for (int e = 0; e < NE; e++) imp[e] = 0.f;
    #pragma unroll
    for (int j = 0; j < 8; j++) {
        const float* gp = &g_gates[(size_t)(base + j) * NE];
        #pragma unroll
        for (int e = 0; e < NE; e++) imp[e] += gp[e];
    }

    float aux = 0.f;
    for (int e = 0; e < NE; e++) {
        sf[tid] = imp[e];
        __syncthreads();
        for (int s = 512; s > 0; s >>= 1) {
            if (tid < s) sf[tid] += sf[tid + s];
            __syncthreads();
        }
        if (tid == 0) {
            int   tot        = sc[e * 1024 + 1023];
            float load       = (float)tot / (float)T_TOKENS;
            float importance = sf[0] / (float)T_TOKENS;
            aux += importance * load;
            int u = tot < CAP ? tot : CAP;
            g_used[e] = u;
            out[y_elems + 1 + e] = (float)u;
        }
        __syncthreads();
    }
    if (tid == 0) out[y_elems] = aux * (float)NE * 0.01f;
}

// ---------------- dispatch: block per token, write fp16 ----------------
__global__ __launch_bounds__(256) void dispatch_kernel(const float* __restrict__ x)
{
    int t = blockIdx.x;
    int r = g_rank[t];
    if (r >= CAP) return;
    int e = g_topidx[t];
    float4 v = ((const float4*)(x + (size_t)t * DM))[threadIdx.x];
    size_t base = ((size_t)e * CAP + r) * (DM / 4) + threadIdx.x;
    ((uint2*)g_buf)[base] = make_uint2(
        packh2(__float2half(v.x), __float2half(v.y)),
        packh2(__float2half(v.z), __float2half(v.w)));
}

// ---------------- weight fp16 hi/lo split (layout preserved [E][K][N]) ----------------
template<bool ISW1>
__global__ __launch_bounds__(256) void convert_split(const float* __restrict__ W)
{
    size_t n4 = (size_t)NE * DM * DH / 4;
    __half* Th = ISW1 ? g_w1h : g_w2h;
    __half* Tl = ISW1 ? g_w1l : g_w2l;
    for (size_t i = (size_t)blockIdx.x * blockDim.x + threadIdx.x; i < n4;
         i += (size_t)gridDim.x * blockDim.x) {
        float4 v = ((const float4*)W)[i];
        __half h0 = __float2half(v.x), h1 = __float2half(v.y);
        __half h2 = __float2half(v.z), h3 = __float2half(v.w);
        __half l0 = __float2half(v.x - __half2float(h0));
        __half l1 = __float2half(v.y - __half2float(h1));
        __half l2 = __float2half(v.z - __half2float(h2));
        __half l3 = __float2half(v.w - __half2float(h3));
        ((uint2*)Th)[i] = make_uint2(packh2(h0, h1), packh2(h2, h3));
        ((uint2*)Tl)[i] = make_uint2(packh2(l0, l1), packh2(l2, l3));
    }
}

// ---------------- mma.sync grouped GEMM (fp16, 2-product) ----------------
// Block tile 128(m) x 256(n), 512 threads, warp tile 64x32 (16 warps, 2x8),
// k-staged 32, 3-stage cp.async pipeline.
// SMEM per stage: A [128 rows][32k] fp16 pad 80B/row; B hi+lo [32k][256n] pad 528B/row.
#define A_PAD 80
#define B_PAD 528
#define OFF_A  0
#define OFF_BH 10240
#define OFF_BL 27136
#define STAGE_STRIDE 44032
#define FFN_SMEM (3 * STAGE_STRIDE)

template<int K, int NFULL>
__device__ __forceinline__ void load_stage(
    unsigned sbase, const __half* A,
    const __half* Bh, const __half* Bl, int k0, int col0, int tid)
{
    {   // A: 512 chunks (128 rows x 4)
        int row = tid >> 2, c = tid & 3;
        unsigned dst = sbase + OFF_A + row * A_PAD + c * 16;
        cp16(dst, A + (size_t)row * K + k0 + c * 8);
    }
    #pragma unroll
    for (int l = 0; l < 4; l++) {   // B: 2048 chunks (hi 1024 + lo 1024)
        int i   = tid + l * 512;
        int arr = i >> 10;
        int rem = i & 1023;
        int kr = rem >> 5, c = rem & 31;
        unsigned dst = sbase + (arr ? OFF_BL : OFF_BH) + kr * B_PAD + c * 16;
        const __half* src = (arr ? Bl : Bh) + (size_t)(k0 + kr) * NFULL + col0 + c * 8;
        cp16(dst, src);
    }
    CP_COMMIT();
}

template<int K, int NFULL, bool RELU, bool FIRST>
__global__ __launch_bounds__(512, 1) void ffn_mma(const float* __restrict__ bias_g)
{
    constexpr int S = K / 32;

    extern __shared__ __align__(128) char smem[];
    const int e    = blockIdx.z;
    const int row0 = blockIdx.y * 128;
    if (row0 >= g_used[e]) return;
    const int col0 = blockIdx.x * 256;

    const __half* A  = (FIRST ? g_buf : g_h) + ((size_t)e * CAP + row0) * K;
    const __half* Bh = (FIRST ? g_w1h : g_w2h) + (size_t)e * K * NFULL;
    const __half* Bl = (FIRST ? g_w1l : g_w2l) + (size_t)e * K * NFULL;

    unsigned sb  = smem_u32(smem);
    int tid  = threadIdx.x;
    int lane = tid & 31;
    int wid  = tid >> 5;
    int wm = (wid & 1) * 64;    // warp m offset (2 warps along m)
    int wn = (wid >> 1) * 32;   // warp n offset (8 warps along n)

    float acc[4][4][4];
    #pragma unroll
    for (int t = 0; t < 4; t++)
        #pragma unroll
        for (int n = 0; n < 4; n++)
            #pragma unroll
            for (int j = 0; j < 4; j++) acc[t][n][j] = 0.f;

    // ldmatrix lane address components
    unsigned a_row  = wm + (lane & 15);
    unsigned a_koff = (lane >> 4) * 16;     // byte offset (k half)
    unsigned b_krow = lane & 15;
    unsigned b_ncol = wn + ((lane & 16) ? 8 : 0);

    load_stage<K, NFULL>(sb, A, Bh, Bl, 0, col0, tid);
    load_stage<K, NFULL>(sb + STAGE_STRIDE, A, Bh, Bl, 32, col0, tid);

    #pragma unroll 1
    for (int s = 0; s < S; s++) {
        if (s == S - 1) { CP_WAIT(0); } else { CP_WAIT(1); }
        __syncthreads();
        if (s + 2 < S)
            load_stage<K, NFULL>(sb + ((s + 2) % 3) * STAGE_STRIDE, A, Bh, Bl,
                                 (s + 2) * 32, col0, tid);
        unsigned ab = sb + (s % 3) * STAGE_STRIDE;
        #pragma unroll
        for (int kk = 0; kk < 2; kk++) {
            unsigned ah[4][4], bh[4][2], bl[4][2];
            #pragma unroll
            for (int t = 0; t < 4; t++)
                ldsm4(ah[t], ab + OFF_A + (a_row + t * 16) * A_PAD + kk * 32 + a_koff);
            #pragma unroll
            for (int h = 0; h < 2; h++) {
                unsigned r[4];
                ldsm4t(r, ab + OFF_BH + (kk * 16 + b_krow) * B_PAD + (b_ncol + h * 16) * 2);
                bh[h * 2][0] = r[0]; bh[h * 2][1] = r[1];
                bh[h * 2 + 1][0] = r[2]; bh[h * 2 + 1][1] = r[3];
            }
            #pragma unroll
            for (int t = 0; t < 4; t++)
                #pragma unroll
                for (int n = 0; n < 4; n++)
                    mma_f16(acc[t][n], ah[t], bh[n]);
            #pragma unroll
            for (int h = 0; h < 2; h++) {
                unsigned r[4];
                ldsm4t(r, ab + OFF_BL + (kk * 16 + b_krow) * B_PAD + (b_ncol + h * 16) * 2);
                bl[h * 2][0] = r[0]; bl[h * 2][1] = r[1];
                bl[h * 2 + 1][0] = r[2]; bl[h * 2 + 1][1] = r[3];
            }
            #pragma unroll
            for (int t = 0; t < 4; t++)
                #pragma unroll
                for (int n = 0; n < 4; n++)
                    mma_f16(acc[t][n], ah[t], bl[n]);
        }
    }

    // epilogue
    const float* bias = bias_g + (size_t)e * NFULL + col0;
    int r0l   = lane >> 2;
    int cpair = (lane & 3) * 2;
    #pragma unroll
    for (int t = 0; t < 4; t++) {
        #pragma unroll
        for (int n = 0; n < 4; n++) {
            int col = wn + n * 8 + cpair;
            float b0 = __ldg(bias + col), b1 = __ldg(bias + col + 1);
            int rowA = row0 + wm + t * 16 + r0l;
            #pragma unroll
            for (int half = 0; half < 2; half++) {
                int rg = rowA + half * 8;
                float v0 = acc[t][n][half * 2]     + b0;
                float v1 = acc[t][n][half * 2 + 1] + b1;
                if (RELU) { v0 = fmaxf(v0, 0.f); v1 = fmaxf(v1, 0.f); }
                size_t idx = ((size_t)e * CAP + rg) * NFULL + col0 + col;
                if (FIRST) {
                    ((unsigned*)g_h)[idx >> 1] =
                        packh2(__float2half(v0), __float2half(v1));
                } else {
                    *(float2*)(g_eout + idx) = make_float2(v0, v1);
                }
            }
        }
    }
}

// ---------------- combine ----------------
__global__ __launch_bounds__(256) void combine_kernel(float* __restrict__ out)
{
    int t = blockIdx.x;
    int r = g_rank[t];
    float4* dst = (float4*)(out + (size_t)t * DM);
    if (r < CAP) {
        int   e = g_topidx[t];
        float v = g_topval[t];
        float4 s = ((const float4*)(g_eout + ((size_t)e * CAP + r) * DM))[threadIdx.x];
        s.x *= v; s.y *= v; s.z *= v; s.w *= v;
        dst[threadIdx.x] = s;
    } else {
        dst[threadIdx.x] = make_float4(0.f, 0.f, 0.f, 0.f);
    }
}

extern "C" void kernel_launch(void* const* d_in, const int* in_sizes, int n_in,
                              void* d_out, int out_size)
{
    const float* x  = (const float*)d_in[0];
    const float* rw = (const float*)d_in[1];
    const float* rb = (const float*)d_in[2];
    const float* w1 = (const float*)d_in[3];
    const float* b1 = (const float*)d_in[4];
    const float* w2 = (const float*)d_in[5];
    const float* b2 = (const float*)d_in[6];
    float* out = (float*)d_out;

    int y_elems = in_sizes[0];

    cudaFuncSetAttribute(ffn_mma<DM, DH, true,  true >,
                         cudaFuncAttributeMaxDynamicSharedMemorySize, FFN_SMEM);
    cudaFuncSetAttribute(ffn_mma<DH, DM, false, false>,
                         cudaFuncAttributeMaxDynamicSharedMemorySize, FFN_SMEM);

    router_kernel<<<T_TOKENS / 8, 256>>>(x, rw, rb);
    scan_kernel<<<1, 1024>>>(out, y_elems);
    dispatch_kernel<<<T_TOKENS, 256>>>(x);
    convert_split<true ><<<4096, 256>>>(w1);
    convert_split<false><<<4096, 256>>>(w2);

    ffn_mma<DM, DH, true,  true ><<<dim3(DH / 256, CAP / 128, NE), 512, FFN_SMEM>>>(b1);
    ffn_mma<DH, DM, false, false><<<dim3(DM / 256, CAP / 128, NE), 512, FFN_SMEM>>>(b2);

    combine_kernel<<<T_TOKENS, 256>>>(out);
}

// round 9
// speedup vs baseline: 2.2851x; 1.5162x over previous
#include <cuda_runtime.h>
#include <cuda_fp16.h>

#define T_TOKENS 8192
#define DM 1024
#define DH 4096
#define NE 8
#define CAP 1280   // int(1.25 * 8192 / 8)

// ---------------- static device scratch (no allocation allowed) ----------------
__device__ __half g_w1 [NE * (size_t)DM * DH];      // W1 fp16 [E][K=DM][N=DH]
__device__ __half g_w2 [NE * (size_t)DH * DM];      // W2 fp16 [E][K=DH][N=DM]
__device__ __half g_buf[NE * (size_t)CAP * DM];     // dispatched tokens fp16
__device__ __half g_h  [NE * (size_t)CAP * DH];     // hidden activations fp16
__device__ float g_part[2 * NE * (size_t)CAP * DM]; // GEMM2 split-K partials
__device__ float g_gates[T_TOKENS * NE];
__device__ float g_topval[T_TOKENS];
__device__ int   g_topidx[T_TOKENS];
__device__ int   g_rank [T_TOKENS];
__device__ int   g_used [NE];

// ---------------- PTX helpers (sm_80-level, valid under compute_103) ------
__device__ __forceinline__ unsigned smem_u32(const void* p) {
    unsigned a;
    asm("{ .reg .u64 t; cvta.to.shared.u64 t, %1; cvt.u32.u64 %0, t; }" : "=r"(a) : "l"(p));
    return a;
}
__device__ __forceinline__ void cp16(unsigned dst, const void* src) {
    asm volatile("cp.async.cg.shared.global [%0], [%1], 16;\n" :: "r"(dst), "l"(src));
}
#define CP_COMMIT() asm volatile("cp.async.commit_group;\n" ::: "memory")
#define CP_WAIT(n)  asm volatile("cp.async.wait_group %0;\n" :: "n"(n) : "memory")

__device__ __forceinline__ void ldsm4(unsigned* r, unsigned addr) {
    asm volatile("ldmatrix.sync.aligned.m8n8.x4.shared.b16 {%0,%1,%2,%3}, [%4];\n"
                 : "=r"(r[0]), "=r"(r[1]), "=r"(r[2]), "=r"(r[3]) : "r"(addr));
}
__device__ __forceinline__ void ldsm4t(unsigned* r, unsigned addr) {
    asm volatile("ldmatrix.sync.aligned.m8n8.x4.trans.shared.b16 {%0,%1,%2,%3}, [%4];\n"
                 : "=r"(r[0]), "=r"(r[1]), "=r"(r[2]), "=r"(r[3]) : "r"(addr));
}
__device__ __forceinline__ void mma_f16(float* d, const unsigned* a, const unsigned* b) {
    asm volatile(
        "mma.sync.aligned.m16n8k16.row.col.f32.f16.f16.f32 "
        "{%0,%1,%2,%3}, {%4,%5,%6,%7}, {%8,%9}, {%0,%1,%2,%3};\n"
        : "+f"(d[0]), "+f"(d[1]), "+f"(d[2]), "+f"(d[3])
        : "r"(a[0]), "r"(a[1]), "r"(a[2]), "r"(a[3]), "r"(b[0]), "r"(b[1]));
}
__device__ __forceinline__ unsigned packh2(__half a, __half b) {
    unsigned short ua = __half_as_ushort(a), ub = __half_as_ushort(b);
    return (unsigned)ua | ((unsigned)ub << 16);
}

// ---------------- router: warp per token ----------------
__global__ __launch_bounds__(256) void router_kernel(
    const float* __restrict__ x,
    const float* __restrict__ rw,
    const float* __restrict__ rb)
{
    int warp = (blockIdx.x * blockDim.x + threadIdx.x) >> 5;
    int lane = threadIdx.x & 31;
    if (warp >= T_TOKENS) return;
    const float* xr = x + (size_t)warp * DM;

    float acc[NE];
    #pragma unroll
    for (int e = 0; e < NE; e++) acc[e] = 0.f;

    #pragma unroll 4
    for (int i = 0; i < DM / 32; i++) {
        int idx = i * 32 + lane;
        float xv = xr[idx];
        const float4* w4 = (const float4*)(rw + idx * NE);
        float4 w0 = w4[0], w1v = w4[1];
        acc[0] += xv * w0.x;  acc[1] += xv * w0.y;
        acc[2] += xv * w0.z;  acc[3] += xv * w0.w;
        acc[4] += xv * w1v.x; acc[5] += xv * w1v.y;
        acc[6] += xv * w1v.z; acc[7] += xv * w1v.w;
    }
    #pragma unroll
    for (int e = 0; e < NE; e++) {
        #pragma unroll
        for (int o = 16; o; o >>= 1)
            acc[e] += __shfl_xor_sync(0xffffffffu, acc[e], o);
    }
    if (lane == 0) {
        float lg[NE];
        float m = -1e30f;
        #pragma unroll
        for (int e = 0; e < NE; e++) { lg[e] = acc[e] + rb[e]; m = fmaxf(m, lg[e]); }
        float g[NE], s = 0.f;
        #pragma unroll
        for (int e = 0; e < NE; e++) { g[e] = __expf(lg[e] - m); s += g[e]; }
        float inv = 1.f / s;
        int   bi = 0;
        float bg = -1.f;
        #pragma unroll
        for (int e = 0; e < NE; e++) {
            g[e] *= inv;
            g_gates[(size_t)warp * NE + e] = g[e];
            if (g[e] > bg) { bg = g[e]; bi = e; }  // strict > => first-max, matches argmax
        }
        g_topidx[warp] = bi;
        g_topval[warp] = bg;
    }
}

// ---------------- scan: single block, ordered per-expert prefix ----------------
__global__ __launch_bounds__(1024) void scan_kernel(float* __restrict__ out, int y_elems)
{
    __shared__ int   sc[NE * 1024];
    __shared__ float sf[1024];
    int tid  = threadIdx.x;
    int base = tid * 8;

    int cnt[NE];
    int eloc[8];
    #pragma unroll
    for (int e = 0; e < NE; e++) cnt[e] = 0;
    #pragma unroll
    for (int j = 0; j < 8; j++) {
        int e = g_topidx[base + j];
        eloc[j] = e;
        cnt[e]++;
    }
    #pragma unroll
    for (int e = 0; e < NE; e++) sc[e * 1024 + tid] = cnt[e];
    __syncthreads();

    for (int off = 1; off < 1024; off <<= 1) {
        int tmp[NE];
        #pragma unroll
        for (int e = 0; e < NE; e++)
            tmp[e] = sc[e * 1024 + tid] + (tid >= off ? sc[e * 1024 + tid - off] : 0);
        __syncthreads();
        #pragma unroll
        for (int e = 0; e < NE; e++) sc[e * 1024 + tid] = tmp[e];
        __syncthreads();
    }

    int off8[NE];
    #pragma unroll
    for (int e = 0; e < NE; e++) off8[e] = sc[e * 1024 + tid] - cnt[e];

    int c2[NE];
    #pragma unroll
    for (int e = 0; e < NE; e++) c2[e] = 0;
    #pragma unroll
    for (int j = 0; j < 8; j++) {
        int e = eloc[j];
        g_rank[base + j] = off8[e] + c2[e];
        c2[e]++;
    }

    float imp[NE];
    #pragma unroll
    for (int e = 0; e < NE; e++) imp[e] = 0.f;
    #pragma unroll
    for (int j = 0; j < 8; j++) {
        const float* gp = &g_gates[(size_t)(base + j) * NE];
        #pragma unroll
        for (int e = 0; e < NE; e++) imp[e] += gp[e];
    }

    float aux = 0.f;
    for (int e = 0; e < NE; e++) {
        sf[tid] = imp[e];
        __syncthreads();
        for (int s = 512; s > 0; s >>= 1) {
            if (tid < s) sf[tid] += sf[tid + s];
            __syncthreads();
        }
        if (tid == 0) {
            int   tot        = sc[e * 1024 + 1023];
            float load       = (float)tot / (float)T_TOKENS;
            float importance = sf[0] / (float)T_TOKENS;
            aux += importance * load;
            int u = tot < CAP ? tot : CAP;
            g_used[e] = u;
            out[y_elems + 1 + e] = (float)u;
        }
        __syncthreads();
    }
    if (tid == 0) out[y_elems] = aux * (float)NE * 0.01f;
}

// ---------------- dispatch: block per token, write fp16 ----------------
__global__ __launch_bounds__(256) void dispatch_kernel(const float* __restrict__ x)
{
    int t = blockIdx.x;
    int r = g_rank[t];
    if (r >= CAP) return;
    int e = g_topidx[t];
    float4 v = ((const float4*)(x + (size_t)t * DM))[threadIdx.x];
    size_t base = ((size_t)e * CAP + r) * (DM / 4) + threadIdx.x;
    ((uint2*)g_buf)[base] = make_uint2(
        packh2(__float2half(v.x), __float2half(v.y)),
        packh2(__float2half(v.z), __float2half(v.w)));
}

// ---------------- weight fp32 -> fp16 convert (both W1, W2; layout preserved) ---
__global__ __launch_bounds__(256) void convert_w(
    const float* __restrict__ w1, const float* __restrict__ w2)
{
    size_t n4 = (size_t)NE * DM * DH / 4;
    for (size_t i = (size_t)blockIdx.x * blockDim.x + threadIdx.x; i < n4;
         i += (size_t)gridDim.x * blockDim.x) {
        float4 a = ((const float4*)w1)[i];
        ((uint2*)g_w1)[i] = make_uint2(packh2(__float2half(a.x), __float2half(a.y)),
                                       packh2(__float2half(a.z), __float2half(a.w)));
        float4 b = ((const float4*)w2)[i];
        ((uint2*)g_w2)[i] = make_uint2(packh2(__float2half(b.x), __float2half(b.y)),
                                       packh2(__float2half(b.z), __float2half(b.w)));
    }
}

// ---------------- mma.sync grouped GEMM (pure fp16) ----------------
// Block tile 128(m) x 256(n), 256 threads, 8 warps (2x4), warp tile 64x64,
// k-staged 32, 5-stage cp.async pipeline. Optional split-K (GEMM2).
// SMEM per stage: A [128 rows][32 k] pad 80B/row = 10240; B [32 k][256 n] pad 528B/row = 16896.
#define A_PAD 80
#define B_PAD 528
#define OFF_B 10240
#define STAGE_STRIDE 27136
#define NSTAGE 5
#define FFN_SMEM (NSTAGE * STAGE_STRIDE)

template<int K, int NFULL>
__device__ __forceinline__ void load_stage(
    unsigned sbase, const __half* A, const __half* B, int k0, int col0, int tid)
{
    #pragma unroll
    for (int l = 0; l < 2; l++) {   // A: 512 chunks (128 rows x 4)
        int i   = tid + l * 256;
        int row = i >> 2, c = i & 3;
        cp16(sbase + row * A_PAD + c * 16, A + (size_t)row * K + k0 + c * 8);
    }
    #pragma unroll
    for (int l = 0; l < 4; l++) {   // B: 1024 chunks (32 k-rows x 32)
        int i  = tid + l * 256;
        int kr = i >> 5, c = i & 31;
        cp16(sbase + OFF_B + kr * B_PAD + c * 16,
             B + (size_t)(k0 + kr) * NFULL + col0 + c * 8);
    }
    CP_COMMIT();
}

template<int K, int NFULL, bool RELU, bool FIRST, int KSPLIT>
__global__ __launch_bounds__(256, 1) void ffn_mma(const float* __restrict__ bias_g)
{
    constexpr int KPER = K / KSPLIT;
    constexpr int S = KPER / 32;

    extern __shared__ __align__(128) char smem[];
    const int e     = blockIdx.z / KSPLIT;
    const int split = blockIdx.z % KSPLIT;
    const int row0  = blockIdx.y * 128;
    if (row0 >= g_used[e]) return;
    const int col0 = blockIdx.x * 256;

    const __half* A = (FIRST ? g_buf : g_h)
                      + ((size_t)e * CAP + row0) * K + (size_t)split * KPER;
    const __half* B = (FIRST ? g_w1 : g_w2)
                      + (size_t)e * K * NFULL + (size_t)split * KPER * NFULL;

    unsigned sb  = smem_u32(smem);
    int tid  = threadIdx.x;
    int lane = tid & 31;
    int wid  = tid >> 5;
    int wm = (wid & 1) * 64;    // 2 warps along m
    int wn = (wid >> 1) * 64;   // 4 warps along n

    float acc[4][8][4];
    #pragma unroll
    for (int t = 0; t < 4; t++)
        #pragma unroll
        for (int n = 0; n < 8; n++)
            #pragma unroll
            for (int j = 0; j < 4; j++) acc[t][n][j] = 0.f;

    // ldmatrix lane address components
    unsigned a_row  = wm + (lane & 15);
    unsigned a_koff = (lane >> 4) * 16;     // byte offset (k half)
    unsigned b_krow = lane & 15;
    unsigned b_ncol = wn + ((lane & 16) ? 8 : 0);

    // prologue: stages 0..3 (4 committed groups)
    #pragma unroll
    for (int p = 0; p < 4; p++)
        load_stage<K, NFULL>(sb + p * STAGE_STRIDE, A, B, p * 32, col0, tid);

    #pragma unroll 1
    for (int s = 0; s < S; s++) {
        CP_WAIT(3);          // commits at top = 4+s; wait(3) => group s complete
        __syncthreads();
        if (s + 4 < S)
            load_stage<K, NFULL>(sb + ((s + 4) % NSTAGE) * STAGE_STRIDE, A, B,
                                 (s + 4) * 32, col0, tid);
        else
            CP_COMMIT();     // empty group keeps the wait accounting uniform

        unsigned ab = sb + (s % NSTAGE) * STAGE_STRIDE;
        #pragma unroll
        for (int kk = 0; kk < 2; kk++) {
            unsigned ah[4][4], bh[8][2];
            #pragma unroll
            for (int t = 0; t < 4; t++)
                ldsm4(ah[t], ab + (a_row + t * 16) * A_PAD + kk * 32 + a_koff);
            #pragma unroll
            for (int h = 0; h < 4; h++) {
                unsigned r[4];
                ldsm4t(r, ab + OFF_B + (kk * 16 + b_krow) * B_PAD + (b_ncol + h * 16) * 2);
                bh[h * 2][0] = r[0]; bh[h * 2][1] = r[1];
                bh[h * 2 + 1][0] = r[2]; bh[h * 2 + 1][1] = r[3];
            }
            #pragma unroll
            for (int t = 0; t < 4; t++)
                #pragma unroll
                for (int n = 0; n < 8; n++)
                    mma_f16(acc[t][n], ah[t], bh[n]);
        }
    }

    // epilogue
    int r0l   = lane >> 2;
    int cpair = (lane & 3) * 2;
    if (FIRST) {
        const float* bias = bias_g + (size_t)e * NFULL + col0;
        #pragma unroll
        for (int t = 0; t < 4; t++) {
            #pragma unroll
            for (int n = 0; n < 8; n++) {
                int col = wn + n * 8 + cpair;
                float b0 = __ldg(bias + col), b1 = __ldg(bias + col + 1);
                int rowA = row0 + wm + t * 16 + r0l;
                #pragma unroll
                for (int half = 0; half < 2; half++) {
                    int rg = rowA + half * 8;
                    float v0 = fmaxf(acc[t][n][half * 2]     + b0, 0.f);
                    float v1 = fmaxf(acc[t][n][half * 2 + 1] + b1, 0.f);
                    size_t idx = ((size_t)e * CAP + rg) * NFULL + col0 + col;
                    ((unsigned*)g_h)[idx >> 1] = packh2(__float2half(v0), __float2half(v1));
                }
            }
        }
    } else {
        float* part = g_part + (size_t)split * NE * (size_t)CAP * DM;
        #pragma unroll
        for (int t = 0; t < 4; t++) {
            #pragma unroll
            for (int n = 0; n < 8; n++) {
                int col = wn + n * 8 + cpair;
                int rowA = row0 + wm + t * 16 + r0l;
                #pragma unroll
                for (int half = 0; half < 2; half++) {
                    int rg = rowA + half * 8;
                    size_t idx = ((size_t)e * CAP + rg) * NFULL + col0 + col;
                    *(float2*)(part + idx) =
                        make_float2(acc[t][n][half * 2], acc[t][n][half * 2 + 1]);
                }
            }
        }
    }
}

// ---------------- combine: sum split-K partials + bias, scale by gate ------
__global__ __launch_bounds__(256) void combine_kernel(
    float* __restrict__ out, const float* __restrict__ b2)
{
    int t = blockIdx.x;
    int r = g_rank[t];
    float4* dst = (float4*)(out + (size_t)t * DM);
    if (r < CAP) {
        int   e = g_topidx[t];
        float v = g_topval[t];
        size_t idx = ((size_t)e * CAP + r) * (DM / 4) + threadIdx.x;
        float4 p0 = ((const float4*)g_part)[idx];
        float4 p1 = ((const float4*)g_part)[idx + (size_t)NE * CAP * DM / 4];
        float4 b  = ((const float4*)(b2 + (size_t)e * DM))[threadIdx.x];
        float4 s;
        s.x = (p0.x + p1.x + b.x) * v;
        s.y = (p0.y + p1.y + b.y) * v;
        s.z = (p0.z + p1.z + b.z) * v;
        s.w = (p0.w + p1.w + b.w) * v;
        dst[threadIdx.x] = s;
    } else {
        dst[threadIdx.x] = make_float4(0.f, 0.f, 0.f, 0.f);
    }
}

extern "C" void kernel_launch(void* const* d_in, const int* in_sizes, int n_in,
                              void* d_out, int out_size)
{
    const float* x  = (const float*)d_in[0];
    const float* rw = (const float*)d_in[1];
    const float* rb = (const float*)d_in[2];
    const float* w1 = (const float*)d_in[3];
    const float* b1 = (const float*)d_in[4];
    const float* w2 = (const float*)d_in[5];
    const float* b2 = (const float*)d_in[6];
    float* out = (float*)d_out;

    int y_elems = in_sizes[0];

    cudaFuncSetAttribute(ffn_mma<DM, DH, true,  true,  1>,
                         cudaFuncAttributeMaxDynamicSharedMemorySize, FFN_SMEM);
    cudaFuncSetAttribute(ffn_mma<DH, DM, false, false, 2>,
                         cudaFuncAttributeMaxDynamicSharedMemorySize, FFN_SMEM);

    router_kernel<<<T_TOKENS / 8, 256>>>(x, rw, rb);
    scan_kernel<<<1, 1024>>>(out, y_elems);
    dispatch_kernel<<<T_TOKENS, 256>>>(x);
    convert_w<<<4096, 256>>>(w1, w2);

    ffn_mma<DM, DH, true,  true,  1><<<dim3(DH / 256, CAP / 128, NE),     256, FFN_SMEM>>>(b1);
    ffn_mma<DH, DM, false, false, 2><<<dim3(DM / 256, CAP / 128, NE * 2), 256, FFN_SMEM>>>(b2);

    combine_kernel<<<T_TOKENS, 256>>>(out, b2);
}

// round 10
// speedup vs baseline: 2.5054x; 1.0964x over previous
#include <cuda_runtime.h>
#include <cuda_fp16.h>

#define T_TOKENS 8192
#define DM 1024
#define DH 4096
#define NE 8
#define CAP 1280   // int(1.25 * 8192 / 8)

// ---------------- static device scratch (no allocation allowed) ----------------
__device__ __half g_w1 [NE * (size_t)DM * DH];      // W1 fp16 [E][K=DM][N=DH]
__device__ __half g_w2 [NE * (size_t)DH * DM];      // W2 fp16 [E][K=DH][N=DM]
__device__ __half g_buf[NE * (size_t)CAP * DM];     // dispatched tokens fp16
__device__ __half g_h  [NE * (size_t)CAP * DH];     // hidden activations fp16
__device__ float g_part[2 * NE * (size_t)CAP * DM]; // GEMM2 split-K partials
__device__ float g_gates[T_TOKENS * NE];
__device__ float g_topval[T_TOKENS];
__device__ int   g_topidx[T_TOKENS];
__device__ int   g_rank [T_TOKENS];
__device__ int   g_used [NE];

// ---------------- PTX helpers (sm_80-level, valid under compute_103) ------
__device__ __forceinline__ unsigned smem_u32(const void* p) {
    unsigned a;
    asm("{ .reg .u64 t; cvta.to.shared.u64 t, %1; cvt.u32.u64 %0, t; }" : "=r"(a) : "l"(p));
    return a;
}
__device__ __forceinline__ void cp16(unsigned dst, const void* src) {
    asm volatile("cp.async.cg.shared.global [%0], [%1], 16;\n" :: "r"(dst), "l"(src));
}
#define CP_COMMIT() asm volatile("cp.async.commit_group;\n" ::: "memory")
#define CP_WAIT(n)  asm volatile("cp.async.wait_group %0;\n" :: "n"(n) : "memory")

__device__ __forceinline__ void ldsm4(unsigned* r, unsigned addr) {
    asm volatile("ldmatrix.sync.aligned.m8n8.x4.shared.b16 {%0,%1,%2,%3}, [%4];\n"
                 : "=r"(r[0]), "=r"(r[1]), "=r"(r[2]), "=r"(r[3]) : "r"(addr));
}
__device__ __forceinline__ void ldsm4t(unsigned* r, unsigned addr) {
    asm volatile("ldmatrix.sync.aligned.m8n8.x4.trans.shared.b16 {%0,%1,%2,%3}, [%4];\n"
                 : "=r"(r[0]), "=r"(r[1]), "=r"(r[2]), "=r"(r[3]) : "r"(addr));
}
__device__ __forceinline__ void mma_f16(float* d, const unsigned* a, const unsigned* b) {
    asm volatile(
        "mma.sync.aligned.m16n8k16.row.col.f32.f16.f16.f32 "
        "{%0,%1,%2,%3}, {%4,%5,%6,%7}, {%8,%9}, {%0,%1,%2,%3};\n"
        : "+f"(d[0]), "+f"(d[1]), "+f"(d[2]), "+f"(d[3])
        : "r"(a[0]), "r"(a[1]), "r"(a[2]), "r"(a[3]), "r"(b[0]), "r"(b[1]));
}
__device__ __forceinline__ unsigned packh2(__half a, __half b) {
    unsigned short ua = __half_as_ushort(a), ub = __half_as_ushort(b);
    return (unsigned)ua | ((unsigned)ub << 16);
}

// ---------------- router: warp per token ----------------
__global__ __launch_bounds__(256) void router_kernel(
    const float* __restrict__ x,
    const float* __restrict__ rw,
    const float* __restrict__ rb)
{
    int warp = (blockIdx.x * blockDim.x + threadIdx.x) >> 5;
    int lane = threadIdx.x & 31;
    if (warp >= T_TOKENS) return;
    const float* xr = x + (size_t)warp * DM;

    float acc[NE];
    #pragma unroll
    for (int e = 0; e < NE; e++) acc[e] = 0.f;

    #pragma unroll 4
    for (int i = 0; i < DM / 32; i++) {
        int idx = i * 32 + lane;
        float xv = xr[idx];
        const float4* w4 = (const float4*)(rw + idx * NE);
        float4 w0 = w4[0], w1v = w4[1];
        acc[0] += xv * w0.x;  acc[1] += xv * w0.y;
        acc[2] += xv * w0.z;  acc[3] += xv * w0.w;
        acc[4] += xv * w1v.x; acc[5] += xv * w1v.y;
        acc[6] += xv * w1v.z; acc[7] += xv * w1v.w;
    }
    #pragma unroll
    for (int e = 0; e < NE; e++) {
        #pragma unroll
        for (int o = 16; o; o >>= 1)
            acc[e] += __shfl_xor_sync(0xffffffffu, acc[e], o);
    }
    if (lane == 0) {
        float lg[NE];
        float m = -1e30f;
        #pragma unroll
        for (int e = 0; e < NE; e++) { lg[e] = acc[e] + rb[e]; m = fmaxf(m, lg[e]); }
        float g[NE], s = 0.f;
        #pragma unroll
        for (int e = 0; e < NE; e++) { g[e] = __expf(lg[e] - m); s += g[e]; }
        float inv = 1.f / s;
        int   bi = 0;
        float bg = -1.f;
        #pragma unroll
        for (int e = 0; e < NE; e++) {
            g[e] *= inv;
            g_gates[(size_t)warp * NE + e] = g[e];
            if (g[e] > bg) { bg = g[e]; bi = e; }  // strict > => first-max, matches argmax
        }
        g_topidx[warp] = bi;
        g_topval[warp] = bg;
    }
}

// ---------------- scan: single block, ordered per-expert prefix ----------------
__global__ __launch_bounds__(1024) void scan_kernel(float* __restrict__ out, int y_elems)
{
    __shared__ int   sc[NE * 1024];
    __shared__ float sf[1024];
    int tid  = threadIdx.x;
    int base = tid * 8;

    int cnt[NE];
    int eloc[8];
    #pragma unroll
    for (int e = 0; e < NE; e++) cnt[e] = 0;
    #pragma unroll
    for (int j = 0; j < 8; j++) {
        int e = g_topidx[base + j];
        eloc[j] = e;
        cnt[e]++;
    }
    #pragma unroll
    for (int e = 0; e < NE; e++) sc[e * 1024 + tid] = cnt[e];
    __syncthreads();

    for (int off = 1; off < 1024; off <<= 1) {
        int tmp[NE];
        #pragma unroll
        for (int e = 0; e < NE; e++)
            tmp[e] = sc[e * 1024 + tid] + (tid >= off ? sc[e * 1024 + tid - off] : 0);
        __syncthreads();
        #pragma unroll
        for (int e = 0; e < NE; e++) sc[e * 1024 + tid] = tmp[e];
        __syncthreads();
    }

    int off8[NE];
    #pragma unroll
    for (int e = 0; e < NE; e++) off8[e] = sc[e * 1024 + tid] - cnt[e];

    int c2[NE];
    #pragma unroll
    for (int e = 0; e < NE; e++) c2[e] = 0;
    #pragma unroll
    for (int j = 0; j < 8; j++) {
        int e = eloc[j];
        g_rank[base + j] = off8[e] + c2[e];
        c2[e]++;
    }

    float imp[NE];
    #pragma unroll
    for (int e = 0; e < NE; e++) imp[e] = 0.f;
    #pragma unroll
    for (int j = 0; j < 8; j++) {
        const float* gp = &g_gates[(size_t)(base + j) * NE];
        #pragma unroll
        for (int e = 0; e < NE; e++) imp[e] += gp[e];
    }

    float aux = 0.f;
    for (int e = 0; e < NE; e++) {
        sf[tid] = imp[e];
        __syncthreads();
        for (int s = 512; s > 0; s >>= 1) {
            if (tid < s) sf[tid] += sf[tid + s];
            __syncthreads();
        }
        if (tid == 0) {
            int   tot        = sc[e * 1024 + 1023];
            float load       = (float)tot / (float)T_TOKENS;
            float importance = sf[0] / (float)T_TOKENS;
            aux += importance * load;
            int u = tot < CAP ? tot : CAP;
            g_used[e] = u;
            out[y_elems + 1 + e] = (float)u;
        }
        __syncthreads();
    }
    if (tid == 0) out[y_elems] = aux * (float)NE * 0.01f;
}

// ---------------- dispatch: block per token, write fp16 ----------------
__global__ __launch_bounds__(256) void dispatch_kernel(const float* __restrict__ x)
{
    int t = blockIdx.x;
    int r = g_rank[t];
    if (r >= CAP) return;
    int e = g_topidx[t];
    float4 v = ((const float4*)(x + (size_t)t * DM))[threadIdx.x];
    size_t base = ((size_t)e * CAP + r) * (DM / 4) + threadIdx.x;
    ((uint2*)g_buf)[base] = make_uint2(
        packh2(__float2half(v.x), __float2half(v.y)),
        packh2(__float2half(v.z), __float2half(v.w)));
}

// ---------------- weight fp32 -> fp16 convert (both W1, W2; layout preserved) ---
__global__ __launch_bounds__(256) void convert_w(
    const float* __restrict__ w1, const float* __restrict__ w2)
{
    size_t n4 = (size_t)NE * DM * DH / 4;
    for (size_t i = (size_t)blockIdx.x * blockDim.x + threadIdx.x; i < n4;
         i += (size_t)gridDim.x * blockDim.x) {
        float4 a = ((const float4*)w1)[i];
        ((uint2*)g_w1)[i] = make_uint2(packh2(__float2half(a.x), __float2half(a.y)),
                                       packh2(__float2half(a.z), __float2half(a.w)));
        float4 b = ((const float4*)w2)[i];
        ((uint2*)g_w2)[i] = make_uint2(packh2(__float2half(b.x), __float2half(b.y)),
                                       packh2(__float2half(b.z), __float2half(b.w)));
    }
}

// ---------------- mma.sync grouped GEMM (pure fp16) ----------------
// Block tile 128(m) x 256(n), 256 threads, 8 warps (2x4), warp tile 64x64,
// k-staged 64, 3-stage cp.async pipeline, register-double-buffered fragments.
// SMEM per stage: A [128 rows][64 k] pad 144B/row = 18432; B [64 k][256 n] pad 528B/row = 33792.
#define A_PAD 144
#define B_PAD 528
#define OFF_B 18432
#define STAGE_STRIDE 52224
#define NSTAGE 3
#define FFN_SMEM (NSTAGE * STAGE_STRIDE)

template<int K, int NFULL>
__device__ __forceinline__ void load_stage(
    unsigned sbase, const __half* A, const __half* B, int k0, int col0, int tid)
{
    #pragma unroll
    for (int l = 0; l < 4; l++) {   // A: 1024 chunks (128 rows x 8)
        int i   = tid + l * 256;
        int row = i >> 3, c = i & 7;
        cp16(sbase + row * A_PAD + c * 16, A + (size_t)row * K + k0 + c * 8);
    }
    #pragma unroll
    for (int l = 0; l < 8; l++) {   // B: 2048 chunks (64 k-rows x 32)
        int i  = tid + l * 256;
        int kr = i >> 5, c = i & 31;
        cp16(sbase + OFF_B + kr * B_PAD + c * 16,
             B + (size_t)(k0 + kr) * NFULL + col0 + c * 8);
    }
    CP_COMMIT();
}

template<int K, int NFULL, bool RELU, bool FIRST, int KSPLIT>
__global__ __launch_bounds__(256, 1) void ffn_mma(const float* __restrict__ bias_g)
{
    constexpr int KPER = K / KSPLIT;
    constexpr int S = KPER / 64;

    extern __shared__ __align__(128) char smem[];
    const int e     = blockIdx.z / KSPLIT;
    const int split = blockIdx.z % KSPLIT;
    const int row0  = blockIdx.y * 128;
    if (row0 >= g_used[e]) return;
    const int col0 = blockIdx.x * 256;

    const __half* A = (FIRST ? g_buf : g_h)
                      + ((size_t)e * CAP + row0) * K + (size_t)split * KPER;
    const __half* B = (FIRST ? g_w1 : g_w2)
                      + (size_t)e * K * NFULL + (size_t)split * KPER * NFULL;

    unsigned sb  = smem_u32(smem);
    int tid  = threadIdx.x;
    int lane = tid & 31;
    int wid  = tid >> 5;
    int wm = (wid & 1) * 64;    // 2 warps along m
    int wn = (wid >> 1) * 64;   // 4 warps along n

    float acc[4][8][4];
    #pragma unroll
    for (int t = 0; t < 4; t++)
        #pragma unroll
        for (int n = 0; n < 8; n++)
            #pragma unroll
            for (int j = 0; j < 4; j++) acc[t][n][j] = 0.f;

    // ldmatrix lane address components
    unsigned a_row  = wm + (lane & 15);
    unsigned a_koff = (lane >> 4) * 16;     // byte offset (k half of 16-k chunk)
    unsigned b_krow = lane & 15;
    unsigned b_ncol = wn + ((lane & 16) ? 8 : 0);

    // double-buffered fragments
    unsigned ah[2][4][4], bh[2][8][2];

    auto ldfrag = [&](unsigned ab, int kk, int buf) {
        #pragma unroll
        for (int t = 0; t < 4; t++)
            ldsm4(ah[buf][t], ab + (a_row + t * 16) * A_PAD + kk * 32 + a_koff);
        #pragma unroll
        for (int h = 0; h < 4; h++) {
            unsigned r[4];
            ldsm4t(r, ab + OFF_B + (kk * 16 + b_krow) * B_PAD + (b_ncol + h * 16) * 2);
            bh[buf][h * 2][0] = r[0]; bh[buf][h * 2][1] = r[1];
            bh[buf][h * 2 + 1][0] = r[2]; bh[buf][h * 2 + 1][1] = r[3];
        }
    };

    // prologue: stages 0,1 in flight
    load_stage<K, NFULL>(sb, A, B, 0, col0, tid);
    load_stage<K, NFULL>(sb + STAGE_STRIDE, A, B, 64, col0, tid);

    #pragma unroll 1
    for (int s = 0; s < S; s++) {
        CP_WAIT(1);
        __syncthreads();
        if (s + 2 < S)
            load_stage<K, NFULL>(sb + ((s + 2) % NSTAGE) * STAGE_STRIDE, A, B,
                                 (s + 2) * 64, col0, tid);
        else
            CP_COMMIT();     // empty group keeps wait accounting uniform

        unsigned ab = sb + (s % NSTAGE) * STAGE_STRIDE;
        ldfrag(ab, 0, 0);
        #pragma unroll
        for (int kk = 0; kk < 4; kk++) {
            int cur = kk & 1;
            if (kk < 3) ldfrag(ab, kk + 1, cur ^ 1);
            #pragma unroll
            for (int t = 0; t < 4; t++)
                #pragma unroll
                for (int n = 0; n < 8; n++)
                    mma_f16(acc[t][n], ah[cur][t], bh[cur][n]);
        }
    }

    // epilogue
    int r0l   = lane >> 2;
    int cpair = (lane & 3) * 2;
    if (FIRST) {
        const float* bias = bias_g + (size_t)e * NFULL + col0;
        #pragma unroll
        for (int t = 0; t < 4; t++) {
            #pragma unroll
            for (int n = 0; n < 8; n++) {
                int col = wn + n * 8 + cpair;
                float b0 = __ldg(bias + col), b1 = __ldg(bias + col + 1);
                int rowA = row0 + wm + t * 16 + r0l;
                #pragma unroll
                for (int half = 0; half < 2; half++) {
                    int rg = rowA + half * 8;
                    float v0 = fmaxf(acc[t][n][half * 2]     + b0, 0.f);
                    float v1 = fmaxf(acc[t][n][half * 2 + 1] + b1, 0.f);
                    size_t idx = ((size_t)e * CAP + rg) * NFULL + col0 + col;
                    ((unsigned*)g_h)[idx >> 1] = packh2(__float2half(v0), __float2half(v1));
                }
            }
        }
    } else {
        float* part = g_part + (size_t)split * NE * (size_t)CAP * DM;
        #pragma unroll
        for (int t = 0; t < 4; t++) {
            #pragma unroll
            for (int n = 0; n < 8; n++) {
                int col = wn + n * 8 + cpair;
                int rowA = row0 + wm + t * 16 + r0l;
                #pragma unroll
                for (int half = 0; half < 2; half++) {
                    int rg = rowA + half * 8;
                    size_t idx = ((size_t)e * CAP + rg) * NFULL + col0 + col;
                    *(float2*)(part + idx) =
                        make_float2(acc[t][n][half * 2], acc[t][n][half * 2 + 1]);
                }
            }
        }
    }
}

// ---------------- combine: sum split-K partials + bias, scale by gate ------
__global__ __launch_bounds__(256) void combine_kernel(
    float* __restrict__ out, const float* __restrict__ b2)
{
    int t = blockIdx.x;
    int r = g_rank[t];
    float4* dst = (float4*)(out + (size_t)t * DM);
    if (r < CAP) {
        int   e = g_topidx[t];
        float v = g_topval[t];
        size_t idx = ((size_t)e * CAP + r) * (DM / 4) + threadIdx.x;
        float4 p0 = ((const float4*)g_part)[idx];
        float4 p1 = ((const float4*)g_part)[idx + (size_t)NE * CAP * DM / 4];
        float4 b  = ((const float4*)(b2 + (size_t)e * DM))[threadIdx.x];
        float4 s;
        s.x = (p0.x + p1.x + b.x) * v;
        s.y = (p0.y + p1.y + b.y) * v;
        s.z = (p0.z + p1.z + b.z) * v;
        s.w = (p0.w + p1.w + b.w) * v;
        dst[threadIdx.x] = s;
    } else {
        dst[threadIdx.x] = make_float4(0.f, 0.f, 0.f, 0.f);
    }
}

extern "C" void kernel_launch(void* const* d_in, const int* in_sizes, int n_in,
                              void* d_out, int out_size)
{
    const float* x  = (const float*)d_in[0];
    const float* rw = (const float*)d_in[1];
    const float* rb = (const float*)d_in[2];
    const float* w1 = (const float*)d_in[3];
    const float* b1 = (const float*)d_in[4];
    const float* w2 = (const float*)d_in[5];
    const float* b2 = (const float*)d_in[6];
    float* out = (float*)d_out;

    int y_elems = in_sizes[0];

    cudaFuncSetAttribute(ffn_mma<DM, DH, true,  true,  1>,
                         cudaFuncAttributeMaxDynamicSharedMemorySize, FFN_SMEM);
    cudaFuncSetAttribute(ffn_mma<DH, DM, false, false, 2>,
                         cudaFuncAttributeMaxDynamicSharedMemorySize, FFN_SMEM);

    router_kernel<<<T_TOKENS / 8, 256>>>(x, rw, rb);
    scan_kernel<<<1, 1024>>>(out, y_elems);
    dispatch_kernel<<<T_TOKENS, 256>>>(x);
    convert_w<<<4096, 256>>>(w1, w2);

    ffn_mma<DM, DH, true,  true,  1><<<dim3(DH / 256, CAP / 128, NE),     256, FFN_SMEM>>>(b1);
    ffn_mma<DH, DM, false, false, 2><<<dim3(DM / 256, CAP / 128, NE * 2), 256, FFN_SMEM>>>(b2);

    combine_kernel<<<T_TOKENS, 256>>>(out, b2);
}